// round 11
// baseline (speedup 1.0000x reference)
#include <cuda_runtime.h>
#include <cstdint>

#define NB 16
#define NN 8192
#define NDIM 384
#define NR 64
#define NG 128
#define MT (NB*NN)   // 131072 rows

// ---------------- scratch (no allocations allowed) ----------------
__device__ __align__(256) float g_h[(size_t)MT*NR];   // 33.5 MB
__device__ __align__(256) float g_y[(size_t)MT*NR];   // 33.5 MB
__device__ __align__(256) int   g_idx[2*MT];          // normalized int32 indices
__device__ int g_is64;

__device__ __forceinline__ float silu_f(float x){ return x / (1.0f + __expf(-x)); }

// ---------------- tf32 helpers ----------------
__device__ __forceinline__ uint32_t tf32_hi(float x){
    uint32_t r; asm("cvt.rna.tf32.f32 %0, %1;" : "=r"(r) : "f"(x)); return r;
}
__device__ __forceinline__ void tf32_split(float x, uint32_t& hi, uint32_t& lo){
    hi = tf32_hi(x);
    lo = tf32_hi(x - __uint_as_float(hi));
}
// D = A(16x8 tf32) * B(8x8 tf32) + D, fp32 accum
__device__ __forceinline__ void mma_tf32(float (&c)[4],
    uint32_t a0, uint32_t a1, uint32_t a2, uint32_t a3,
    uint32_t b0, uint32_t b1)
{
    asm volatile("mma.sync.aligned.m16n8k8.row.col.f32.tf32.tf32.f32 "
        "{%0,%1,%2,%3}, {%4,%5,%6,%7}, {%8,%9}, {%0,%1,%2,%3};\n"
        : "+f"(c[0]), "+f"(c[1]), "+f"(c[2]), "+f"(c[3])
        : "r"(a0), "r"(a1), "r"(a2), "r"(a3), "r"(b0), "r"(b1));
}
__device__ __forceinline__ void fma4x4(float (&acc)[4][4], float4 a, float4 b){
    float av[4] = {a.x,a.y,a.z,a.w};
    float bv[4] = {b.x,b.y,b.z,b.w};
    #pragma unroll
    for (int i=0;i<4;i++)
        #pragma unroll
        for (int j=0;j<4;j++)
            acc[i][j] += av[i]*bv[j];
}

// ---------------- idx dtype probe + normalize ----------------
__global__ void probe_idx_kernel(const unsigned int* __restrict__ w){
    __shared__ int ok;
    if (threadIdx.x == 0) ok = 1;
    __syncthreads();
    if (w[2*threadIdx.x + 1] != 0u) ok = 0;
    __syncthreads();
    if (threadIdx.x == 0) g_is64 = ok;
}
__global__ void convert_idx_kernel(const void* __restrict__ p){
    int i = blockIdx.x*blockDim.x + threadIdx.x;
    if (i >= 2*MT) return;
    if (g_is64) g_idx[i] = (int)((const long long*)p)[i];
    else        g_idx[i] = ((const int*)p)[i];
}

// ================= K1: h = silu(X @ Wd^T + bd), tf32 split-3 tensor cores ====
// C[131072,64] = A[131072,384] * Wd[64,384]^T
// BM=256, BN=64, BK=32. 8 warps, each 64m x 32n. m16n8k8 mma.
// Smem layout: row stride 40 floats (=8 mod 32 -> conflict-free frag LDS.64);
// within a row, chunk c (8 k-values) stored permuted {k0,k4,k1,k5,k2,k6,k3,k7}
// so one LDS.64 at [row][c*8 + t4*2] yields {A[row][k0+t4], A[row][k0+t4+4]}.
#define DK_SA 40
#define DK_SMEM ((256*DK_SA + 64*DK_SA)*4)   // 51200 B
__global__ __launch_bounds__(256) void down_kernel(
    const float* __restrict__ A, const float* __restrict__ Wd,
    const float* __restrict__ bd)
{
    extern __shared__ float sm[];
    float* As = sm;               // [256][40]
    float* Bs = sm + 256*DK_SA;   // [64][40]
    const int tid  = threadIdx.x;
    const int wid  = tid >> 5, lane = tid & 31;
    const int g    = lane >> 2, t4 = lane & 3;
    const int wm   = wid & 3,   wn = wid >> 2;   // 4 x 2 warp grid
    const int m0   = blockIdx.x * 256;

    const int lrow = tid >> 2, lc = tid & 3;     // load mapping (items of 8 floats)
    const float* Abase = A + (size_t)m0 * NDIM;

    float4 pa[4][2];
    float4 pb[2];

    // prefetch stage 0
    {
        #pragma unroll
        for (int i=0;i<4;i++){
            const float* p = Abase + (size_t)(lrow + i*64)*NDIM + lc*8;
            pa[i][0] = *(const float4*)p;
            pa[i][1] = *(const float4*)(p+4);
        }
        const float* p = Wd + (size_t)lrow*NDIM + lc*8;
        pb[0] = *(const float4*)p;
        pb[1] = *(const float4*)(p+4);
    }

    float acc[4][4][4] = {};   // [mt][nt][frag]

    for (int s = 0; s < 12; s++){
        __syncthreads();
        // store permuted
        #pragma unroll
        for (int i=0;i<4;i++){
            float* d = As + (lrow + i*64)*DK_SA + lc*8;
            *(float4*)(d)   = make_float4(pa[i][0].x, pa[i][1].x, pa[i][0].y, pa[i][1].y);
            *(float4*)(d+4) = make_float4(pa[i][0].z, pa[i][1].z, pa[i][0].w, pa[i][1].w);
        }
        {
            float* d = Bs + lrow*DK_SA + lc*8;
            *(float4*)(d)   = make_float4(pb[0].x, pb[1].x, pb[0].y, pb[1].y);
            *(float4*)(d+4) = make_float4(pb[0].z, pb[1].z, pb[0].w, pb[1].w);
        }
        __syncthreads();

        if (s < 11){   // prefetch next stage under the mma work
            #pragma unroll
            for (int i=0;i<4;i++){
                const float* p = Abase + (size_t)(lrow + i*64)*NDIM + (s+1)*32 + lc*8;
                pa[i][0] = *(const float4*)p;
                pa[i][1] = *(const float4*)(p+4);
            }
            const float* p = Wd + (size_t)lrow*NDIM + (s+1)*32 + lc*8;
            pb[0] = *(const float4*)p;
            pb[1] = *(const float4*)(p+4);
        }

        #pragma unroll 2
        for (int c8 = 0; c8 < 4; c8++){
            uint32_t ah[4][4], al[4][4];
            #pragma unroll
            for (int mt=0; mt<4; mt++){
                const float* base = As + (wm*64 + mt*16 + g)*DK_SA + c8*8 + t4*2;
                float2 r0 = *(const float2*)base;
                float2 r8 = *(const float2*)(base + 8*DK_SA);
                tf32_split(r0.x, ah[mt][0], al[mt][0]);   // (g,   k)
                tf32_split(r8.x, ah[mt][1], al[mt][1]);   // (g+8, k)
                tf32_split(r0.y, ah[mt][2], al[mt][2]);   // (g,   k+4)
                tf32_split(r8.y, ah[mt][3], al[mt][3]);   // (g+8, k+4)
            }
            uint32_t bh[4][2], bl[4][2];
            #pragma unroll
            for (int nt=0; nt<4; nt++){
                const float* base = Bs + (wn*32 + nt*8 + g)*DK_SA + c8*8 + t4*2;
                float2 b = *(const float2*)base;
                tf32_split(b.x, bh[nt][0], bl[nt][0]);
                tf32_split(b.y, bh[nt][1], bl[nt][1]);
            }
            #pragma unroll
            for (int mt=0; mt<4; mt++)
                #pragma unroll
                for (int nt=0; nt<4; nt++){
                    mma_tf32(acc[mt][nt], al[mt][0],al[mt][1],al[mt][2],al[mt][3], bh[nt][0],bh[nt][1]);
                    mma_tf32(acc[mt][nt], ah[mt][0],ah[mt][1],ah[mt][2],ah[mt][3], bl[nt][0],bl[nt][1]);
                    mma_tf32(acc[mt][nt], ah[mt][0],ah[mt][1],ah[mt][2],ah[mt][3], bh[nt][0],bh[nt][1]);
                }
        }
    }

    // epilogue: bias + silu -> g_h
    #pragma unroll
    for (int mt=0; mt<4; mt++){
        int row = m0 + wm*64 + mt*16 + g;
        #pragma unroll
        for (int nt=0; nt<4; nt++){
            int col = wn*32 + nt*8 + t4*2;
            float b0 = __ldg(bd+col), b1 = __ldg(bd+col+1);
            float* o = g_h + (size_t)row*NR + col;
            *(float2*)o =
                make_float2(silu_f(acc[mt][nt][0]+b0), silu_f(acc[mt][nt][1]+b1));
            *(float2*)(o + 8*NR) =
                make_float2(silu_f(acc[mt][nt][2]+b0), silu_f(acc[mt][nt][3]+b1));
        }
    }
}

// ================= K2: fused per-(b,g) branch (unchanged, FFMA) ==============
#define K3_SMEM (5*64*68*4 + 3*64*4)
__global__ __launch_bounds__(256) void group_kernel(
    const float* __restrict__ subU, const float* __restrict__ Wa,
    const float* __restrict__ ba, const float* __restrict__ gamma,
    const float* __restrict__ beta)
{
    extern __shared__ float sm[];
    float* Ug  = sm;
    float* Ut  = Ug  + 64*68;
    float* Xs  = Ut  + 64*68;
    float* Fs  = Xs  + 64*68;
    float* WaT = Fs  + 64*68;
    float* sGa = WaT + 64*68;
    float* sBe = sGa + 64;
    float* sBa = sBe + 64;

    const int tid = threadIdx.x;
    const int tx = tid & 15, ty = tid >> 4;
    const int bg = blockIdx.x;
    const int b = bg >> 7, g = bg & 127;
    const float* U = subU + ((size_t)(16 + b)*128 + g)*4096;  // sub_U[1][b][g]

    const int row = tid >> 2;
    const int c0  = (tid & 3) * 16;
    const int src = g_idx[b*NN + g*64 + row];                 // idx[0]
    const float* hsrc = g_h + ((size_t)b*NN + src)*NR;

    #pragma unroll
    for (int c = 0; c < 16; c += 4){
        float4 u = *(const float4*)(U + row*64 + c0 + c);
        *(float4*)&Ug[row*68 + c0 + c] = u;
        Ut[(c0+c+0)*68 + row] = u.x;
        Ut[(c0+c+1)*68 + row] = u.y;
        Ut[(c0+c+2)*68 + row] = u.z;
        Ut[(c0+c+3)*68 + row] = u.w;
        float4 w = *(const float4*)(Wa + row*64 + c0 + c);
        WaT[(c0+c+0)*68 + row] = w.x;
        WaT[(c0+c+1)*68 + row] = w.y;
        WaT[(c0+c+2)*68 + row] = w.z;
        WaT[(c0+c+3)*68 + row] = w.w;
        float4 x = *(const float4*)(hsrc + c0 + c);
        *(float4*)&Xs[row*68 + c0 + c] = x;
    }
    if (tid < 64){ sGa[tid]=gamma[tid]; sBe[tid]=beta[tid]; sBa[tid]=ba[tid]; }
    __syncthreads();

    float accF[4][4] = {};
    #pragma unroll 8
    for (int t = 0; t < 64; t++){
        float4 af = *(const float4*)&Ug[t*68 + ty*4];
        float4 bf = *(const float4*)&Xs[t*68 + tx*4];
        fma4x4(accF, af, bf);
    }
    #pragma unroll
    for (int i=0;i<4;i++)
        *(float4*)&Fs[(ty*4+i)*68 + tx*4] =
            make_float4(accF[i][0],accF[i][1],accF[i][2],accF[i][3]);
    __syncthreads();

    float ssum=0.f, ssq=0.f;
    #pragma unroll
    for (int c=0;c<16;c+=4){
        float4 f = *(const float4*)&Fs[row*68 + c0 + c];
        ssum += f.x+f.y+f.z+f.w;
        ssq  += f.x*f.x + f.y*f.y + f.z*f.z + f.w*f.w;
    }
    ssum += __shfl_xor_sync(0xffffffffu, ssum, 1);
    ssq  += __shfl_xor_sync(0xffffffffu, ssq , 1);
    ssum += __shfl_xor_sync(0xffffffffu, ssum, 2);
    ssq  += __shfl_xor_sync(0xffffffffu, ssq , 2);
    float mean = ssum * (1.0f/64.0f);
    float var  = ssq  * (1.0f/64.0f) - mean*mean;
    float rstd = rsqrtf(var + 1e-5f);
    #pragma unroll
    for (int c=0;c<16;c+=4){
        float4 f = *(const float4*)&Fs[row*68 + c0 + c];
        Xs[(c0+c+0)*68 + row] = (f.x-mean)*rstd*sGa[c0+c+0] + sBe[c0+c+0];
        Xs[(c0+c+1)*68 + row] = (f.y-mean)*rstd*sGa[c0+c+1] + sBe[c0+c+1];
        Xs[(c0+c+2)*68 + row] = (f.z-mean)*rstd*sGa[c0+c+2] + sBe[c0+c+2];
        Xs[(c0+c+3)*68 + row] = (f.w-mean)*rstd*sGa[c0+c+3] + sBe[c0+c+3];
    }
    __syncthreads();

    float accG[4][4] = {};
    #pragma unroll 8
    for (int t = 0; t < 64; t++){
        float4 af = *(const float4*)&Xs[t*68 + ty*4];
        float4 bf = *(const float4*)&WaT[t*68 + tx*4];
        fma4x4(accG, af, bf);
    }
    #pragma unroll
    for (int i=0;i<4;i++){
        float4 o;
        o.x = accF[i][0] + silu_f(accG[i][0] + sBa[tx*4+0]);
        o.y = accF[i][1] + silu_f(accG[i][1] + sBa[tx*4+1]);
        o.z = accF[i][2] + silu_f(accG[i][2] + sBa[tx*4+2]);
        o.w = accF[i][3] + silu_f(accG[i][3] + sBa[tx*4+3]);
        *(float4*)&Fs[(ty*4+i)*68 + tx*4] = o;
    }
    __syncthreads();

    float accY[4][4] = {};
    #pragma unroll 8
    for (int t = 0; t < 64; t++){
        float4 af = *(const float4*)&Ut[t*68 + ty*4];
        float4 bf = *(const float4*)&Fs[t*68 + tx*4];
        fma4x4(accY, af, bf);
    }
    float* yout = g_y + ((size_t)b*NN + g*64)*NR;
    #pragma unroll
    for (int i=0;i<4;i++)
        *(float4*)(yout + (size_t)(ty*4+i)*NR + tx*4) =
            make_float4(accY[i][0],accY[i][1],accY[i][2],accY[i][3]);
}

// ================= K3: out = (h + y + gather(y,idx1)) @ Wu^T + bu ===========
// tf32 split-3 tensor cores, combine fused into the A-tile load.
// BM=64, BN=384 (full N so A rows are read exactly once), K=64 single pass.
// 8 warps, each 64m x 48n (6 n-tiles).
#define UK_SA 72
#define UK_SMEM ((64*UK_SA + 384*UK_SA + 384)*4)   // 130560 B
__global__ __launch_bounds__(256) void up_kernel(
    const float* __restrict__ Wu, const float* __restrict__ bu,
    float* __restrict__ out)
{
    extern __shared__ float sm[];
    float* As  = sm;                 // [64][72]
    float* Bs  = sm + 64*UK_SA;      // [384][72]
    float* sBu = Bs + 384*UK_SA;     // [384]
    const int tid = threadIdx.x;
    const int wid = tid >> 5, lane = tid & 31;
    const int g = lane >> 2, t4 = lane & 3;
    const int m0 = blockIdx.x * 64;

    // A load: fused h + y + gather(y, idx1), permuted store. 512 items of 8 floats.
    #pragma unroll
    for (int i=0;i<2;i++){
        int item = tid + i*256;
        int row = item >> 3, cc = item & 7;
        int grow = m0 + row;
        int b = grow >> 13, j = grow & (NN-1);
        int src = g_idx[MT + (b<<13) + j];
        const float* hp = g_h + (size_t)grow*NR + cc*8;
        const float* yp = g_y + (size_t)grow*NR + cc*8;
        const float* gp = g_y + ((size_t)((b<<13) + src))*NR + cc*8;
        float4 h0 = *(const float4*)hp,     h1 = *(const float4*)(hp+4);
        float4 y0 = *(const float4*)yp,     y1 = *(const float4*)(yp+4);
        float4 q0 = *(const float4*)gp,     q1 = *(const float4*)(gp+4);
        float4 v0 = make_float4(h0.x+y0.x+q0.x, h0.y+y0.y+q0.y,
                                h0.z+y0.z+q0.z, h0.w+y0.w+q0.w);
        float4 v1 = make_float4(h1.x+y1.x+q1.x, h1.y+y1.y+q1.y,
                                h1.z+y1.z+q1.z, h1.w+y1.w+q1.w);
        float* d = As + row*UK_SA + cc*8;
        *(float4*)(d)   = make_float4(v0.x, v1.x, v0.y, v1.y);
        *(float4*)(d+4) = make_float4(v0.z, v1.z, v0.w, v1.w);
    }
    // B load: Wu[384][64], 3072 items / 256 threads = 12 iters
    #pragma unroll
    for (int i=0;i<12;i++){
        int item = tid + i*256;
        int n = item >> 3, cc = item & 7;
        const float* p = Wu + (size_t)n*NR + cc*8;
        float4 v0 = *(const float4*)p, v1 = *(const float4*)(p+4);
        float* d = Bs + n*UK_SA + cc*8;
        *(float4*)(d)   = make_float4(v0.x, v1.x, v0.y, v1.y);
        *(float4*)(d+4) = make_float4(v0.z, v1.z, v0.w, v1.w);
    }
    for (int i=tid; i<384; i+=256) sBu[i] = bu[i];
    __syncthreads();

    float acc[4][6][4] = {};   // [mt][nt][frag]
    #pragma unroll 2
    for (int c8 = 0; c8 < 8; c8++){
        uint32_t ah[4][4], al[4][4];
        #pragma unroll
        for (int mt=0; mt<4; mt++){
            const float* base = As + (mt*16 + g)*UK_SA + c8*8 + t4*2;
            float2 r0 = *(const float2*)base;
            float2 r8 = *(const float2*)(base + 8*UK_SA);
            tf32_split(r0.x, ah[mt][0], al[mt][0]);
            tf32_split(r8.x, ah[mt][1], al[mt][1]);
            tf32_split(r0.y, ah[mt][2], al[mt][2]);
            tf32_split(r8.y, ah[mt][3], al[mt][3]);
        }
        uint32_t bh[6][2], bl[6][2];
        #pragma unroll
        for (int nt=0; nt<6; nt++){
            const float* base = Bs + (wid*48 + nt*8 + g)*UK_SA + c8*8 + t4*2;
            float2 bv = *(const float2*)base;
            tf32_split(bv.x, bh[nt][0], bl[nt][0]);
            tf32_split(bv.y, bh[nt][1], bl[nt][1]);
        }
        #pragma unroll
        for (int mt=0; mt<4; mt++)
            #pragma unroll
            for (int nt=0; nt<6; nt++){
                mma_tf32(acc[mt][nt], al[mt][0],al[mt][1],al[mt][2],al[mt][3], bh[nt][0],bh[nt][1]);
                mma_tf32(acc[mt][nt], ah[mt][0],ah[mt][1],ah[mt][2],ah[mt][3], bl[nt][0],bl[nt][1]);
                mma_tf32(acc[mt][nt], ah[mt][0],ah[mt][1],ah[mt][2],ah[mt][3], bh[nt][0],bh[nt][1]);
            }
    }

    // epilogue: bias -> out
    #pragma unroll
    for (int mt=0; mt<4; mt++){
        int row = m0 + mt*16 + g;
        #pragma unroll
        for (int nt=0; nt<6; nt++){
            int col = wid*48 + nt*8 + t4*2;
            float b0 = sBu[col], b1 = sBu[col+1];
            float* o = out + (size_t)row*NDIM + col;
            *(float2*)o          = make_float2(acc[mt][nt][0]+b0, acc[mt][nt][1]+b1);
            *(float2*)(o + 8*NDIM) = make_float2(acc[mt][nt][2]+b0, acc[mt][nt][3]+b1);
        }
    }
}

// ---------------- launch ----------------
extern "C" void kernel_launch(void* const* d_in, const int* in_sizes, int n_in,
                              void* d_out, int out_size)
{
    const float* input = (const float*)d_in[0];
    const float* subU  = (const float*)d_in[1];
    const void*  idx   = d_in[2];
    const float* Wd    = (const float*)d_in[3];
    const float* bd    = (const float*)d_in[4];
    const float* Wu    = (const float*)d_in[5];
    const float* bu    = (const float*)d_in[6];
    const float* Wa    = (const float*)d_in[7];
    const float* ba    = (const float*)d_in[8];
    const float* ga    = (const float*)d_in[9];
    const float* be    = (const float*)d_in[10];
    float* out = (float*)d_out;
    (void)in_sizes; (void)n_in; (void)out_size;

    cudaFuncSetAttribute(down_kernel,  cudaFuncAttributeMaxDynamicSharedMemorySize, DK_SMEM);
    cudaFuncSetAttribute(group_kernel, cudaFuncAttributeMaxDynamicSharedMemorySize, K3_SMEM);
    cudaFuncSetAttribute(up_kernel,    cudaFuncAttributeMaxDynamicSharedMemorySize, UK_SMEM);

    probe_idx_kernel<<<1, 128>>>((const unsigned int*)idx);
    convert_idx_kernel<<<(2*MT + 255)/256, 256>>>(idx);
    down_kernel<<<MT/256, 256, DK_SMEM>>>(input, Wd, bd);
    group_kernel<<<NB*NG, 256, K3_SMEM>>>(subU, Wa, ba, ga, be);
    up_kernel<<<MT/64, 256, UK_SMEM>>>(Wu, bu, out);
}

// round 12
// speedup vs baseline: 1.0001x; 1.0001x over previous
#include <cuda_runtime.h>
#include <cstdint>

#define NB 16
#define NN 8192
#define NDIM 384
#define NR 64
#define NG 128
#define MT (NB*NN)   // 131072 rows

// ---------------- scratch (no allocations allowed) ----------------
__device__ __align__(256) float g_h[(size_t)MT*NR];   // 33.5 MB
__device__ __align__(256) float g_y[(size_t)MT*NR];   // 33.5 MB
__device__ __align__(256) int   g_idx[2*MT];          // normalized int32 indices
__device__ int g_is64;

__device__ __forceinline__ float silu_f(float x){ return x / (1.0f + __expf(-x)); }

// ---------------- tf32 helpers ----------------
__device__ __forceinline__ uint32_t tf32_hi(float x){
    uint32_t r; asm("cvt.rna.tf32.f32 %0, %1;" : "=r"(r) : "f"(x)); return r;
}
__device__ __forceinline__ void tf32_split(float x, uint32_t& hi, uint32_t& lo){
    hi = tf32_hi(x);
    lo = tf32_hi(x - __uint_as_float(hi));
}
// D = A(16x8 tf32) * B(8x8 tf32) + D, fp32 accum
__device__ __forceinline__ void mma_tf32(float (&c)[4],
    uint32_t a0, uint32_t a1, uint32_t a2, uint32_t a3,
    uint32_t b0, uint32_t b1)
{
    asm volatile("mma.sync.aligned.m16n8k8.row.col.f32.tf32.tf32.f32 "
        "{%0,%1,%2,%3}, {%4,%5,%6,%7}, {%8,%9}, {%0,%1,%2,%3};\n"
        : "+f"(c[0]), "+f"(c[1]), "+f"(c[2]), "+f"(c[3])
        : "r"(a0), "r"(a1), "r"(a2), "r"(a3), "r"(b0), "r"(b1));
}
__device__ __forceinline__ void fma4x4(float (&acc)[4][4], float4 a, float4 b){
    float av[4] = {a.x,a.y,a.z,a.w};
    float bv[4] = {b.x,b.y,b.z,b.w};
    #pragma unroll
    for (int i=0;i<4;i++)
        #pragma unroll
        for (int j=0;j<4;j++)
            acc[i][j] += av[i]*bv[j];
}

// ---------------- idx dtype probe + normalize ----------------
__global__ void probe_idx_kernel(const unsigned int* __restrict__ w){
    __shared__ int ok;
    if (threadIdx.x == 0) ok = 1;
    __syncthreads();
    if (w[2*threadIdx.x + 1] != 0u) ok = 0;
    __syncthreads();
    if (threadIdx.x == 0) g_is64 = ok;
}
__global__ void convert_idx_kernel(const void* __restrict__ p){
    int i = blockIdx.x*blockDim.x + threadIdx.x;
    if (i >= 2*MT) return;
    if (g_is64) g_idx[i] = (int)((const long long*)p)[i];
    else        g_idx[i] = ((const int*)p)[i];
}

// ================= K1: h = silu(X @ Wd^T + bd), tf32 split-3 tensor cores ====
// C[131072,64] = A[131072,384] * Wd[64,384]^T
// BM=256, BN=64, BK=32. 8 warps, each 64m x 32n. m16n8k8 mma.
// Smem layout: row stride 40 floats (=8 mod 32 -> conflict-free frag LDS.64);
// within a row, chunk c (8 k-values) stored permuted {k0,k4,k1,k5,k2,k6,k3,k7}
// so one LDS.64 at [row][c*8 + t4*2] yields {A[row][k0+t4], A[row][k0+t4+4]}.
#define DK_SA 40
#define DK_SMEM ((256*DK_SA + 64*DK_SA)*4)   // 51200 B
__global__ __launch_bounds__(256) void down_kernel(
    const float* __restrict__ A, const float* __restrict__ Wd,
    const float* __restrict__ bd)
{
    extern __shared__ float sm[];
    float* As = sm;               // [256][40]
    float* Bs = sm + 256*DK_SA;   // [64][40]
    const int tid  = threadIdx.x;
    const int wid  = tid >> 5, lane = tid & 31;
    const int g    = lane >> 2, t4 = lane & 3;
    const int wm   = wid & 3,   wn = wid >> 2;   // 4 x 2 warp grid
    const int m0   = blockIdx.x * 256;

    const int lrow = tid >> 2, lc = tid & 3;     // load mapping (items of 8 floats)
    const float* Abase = A + (size_t)m0 * NDIM;

    float4 pa[4][2];
    float4 pb[2];

    // prefetch stage 0
    {
        #pragma unroll
        for (int i=0;i<4;i++){
            const float* p = Abase + (size_t)(lrow + i*64)*NDIM + lc*8;
            pa[i][0] = *(const float4*)p;
            pa[i][1] = *(const float4*)(p+4);
        }
        const float* p = Wd + (size_t)lrow*NDIM + lc*8;
        pb[0] = *(const float4*)p;
        pb[1] = *(const float4*)(p+4);
    }

    float acc[4][4][4] = {};   // [mt][nt][frag]

    for (int s = 0; s < 12; s++){
        __syncthreads();
        // store permuted
        #pragma unroll
        for (int i=0;i<4;i++){
            float* d = As + (lrow + i*64)*DK_SA + lc*8;
            *(float4*)(d)   = make_float4(pa[i][0].x, pa[i][1].x, pa[i][0].y, pa[i][1].y);
            *(float4*)(d+4) = make_float4(pa[i][0].z, pa[i][1].z, pa[i][0].w, pa[i][1].w);
        }
        {
            float* d = Bs + lrow*DK_SA + lc*8;
            *(float4*)(d)   = make_float4(pb[0].x, pb[1].x, pb[0].y, pb[1].y);
            *(float4*)(d+4) = make_float4(pb[0].z, pb[1].z, pb[0].w, pb[1].w);
        }
        __syncthreads();

        if (s < 11){   // prefetch next stage under the mma work
            #pragma unroll
            for (int i=0;i<4;i++){
                const float* p = Abase + (size_t)(lrow + i*64)*NDIM + (s+1)*32 + lc*8;
                pa[i][0] = *(const float4*)p;
                pa[i][1] = *(const float4*)(p+4);
            }
            const float* p = Wd + (size_t)lrow*NDIM + (s+1)*32 + lc*8;
            pb[0] = *(const float4*)p;
            pb[1] = *(const float4*)(p+4);
        }

        #pragma unroll 2
        for (int c8 = 0; c8 < 4; c8++){
            uint32_t ah[4][4], al[4][4];
            #pragma unroll
            for (int mt=0; mt<4; mt++){
                const float* base = As + (wm*64 + mt*16 + g)*DK_SA + c8*8 + t4*2;
                float2 r0 = *(const float2*)base;
                float2 r8 = *(const float2*)(base + 8*DK_SA);
                tf32_split(r0.x, ah[mt][0], al[mt][0]);   // (g,   k)
                tf32_split(r8.x, ah[mt][1], al[mt][1]);   // (g+8, k)
                tf32_split(r0.y, ah[mt][2], al[mt][2]);   // (g,   k+4)
                tf32_split(r8.y, ah[mt][3], al[mt][3]);   // (g+8, k+4)
            }
            uint32_t bh[4][2], bl[4][2];
            #pragma unroll
            for (int nt=0; nt<4; nt++){
                const float* base = Bs + (wn*32 + nt*8 + g)*DK_SA + c8*8 + t4*2;
                float2 b = *(const float2*)base;
                tf32_split(b.x, bh[nt][0], bl[nt][0]);
                tf32_split(b.y, bh[nt][1], bl[nt][1]);
            }
            #pragma unroll
            for (int mt=0; mt<4; mt++)
                #pragma unroll
                for (int nt=0; nt<4; nt++){
                    mma_tf32(acc[mt][nt], al[mt][0],al[mt][1],al[mt][2],al[mt][3], bh[nt][0],bh[nt][1]);
                    mma_tf32(acc[mt][nt], ah[mt][0],ah[mt][1],ah[mt][2],ah[mt][3], bl[nt][0],bl[nt][1]);
                    mma_tf32(acc[mt][nt], ah[mt][0],ah[mt][1],ah[mt][2],ah[mt][3], bh[nt][0],bh[nt][1]);
                }
        }
    }

    // epilogue: bias + silu -> g_h
    #pragma unroll
    for (int mt=0; mt<4; mt++){
        int row = m0 + wm*64 + mt*16 + g;
        #pragma unroll
        for (int nt=0; nt<4; nt++){
            int col = wn*32 + nt*8 + t4*2;
            float b0 = __ldg(bd+col), b1 = __ldg(bd+col+1);
            float* o = g_h + (size_t)row*NR + col;
            *(float2*)o =
                make_float2(silu_f(acc[mt][nt][0]+b0), silu_f(acc[mt][nt][1]+b1));
            *(float2*)(o + 8*NR) =
                make_float2(silu_f(acc[mt][nt][2]+b0), silu_f(acc[mt][nt][3]+b1));
        }
    }
}

// ================= K2: fused per-(b,g) branch (unchanged, FFMA) ==============
#define K3_SMEM (5*64*68*4 + 3*64*4)
__global__ __launch_bounds__(256) void group_kernel(
    const float* __restrict__ subU, const float* __restrict__ Wa,
    const float* __restrict__ ba, const float* __restrict__ gamma,
    const float* __restrict__ beta)
{
    extern __shared__ float sm[];
    float* Ug  = sm;
    float* Ut  = Ug  + 64*68;
    float* Xs  = Ut  + 64*68;
    float* Fs  = Xs  + 64*68;
    float* WaT = Fs  + 64*68;
    float* sGa = WaT + 64*68;
    float* sBe = sGa + 64;
    float* sBa = sBe + 64;

    const int tid = threadIdx.x;
    const int tx = tid & 15, ty = tid >> 4;
    const int bg = blockIdx.x;
    const int b = bg >> 7, g = bg & 127;
    const float* U = subU + ((size_t)(16 + b)*128 + g)*4096;  // sub_U[1][b][g]

    const int row = tid >> 2;
    const int c0  = (tid & 3) * 16;
    const int src = g_idx[b*NN + g*64 + row];                 // idx[0]
    const float* hsrc = g_h + ((size_t)b*NN + src)*NR;

    #pragma unroll
    for (int c = 0; c < 16; c += 4){
        float4 u = *(const float4*)(U + row*64 + c0 + c);
        *(float4*)&Ug[row*68 + c0 + c] = u;
        Ut[(c0+c+0)*68 + row] = u.x;
        Ut[(c0+c+1)*68 + row] = u.y;
        Ut[(c0+c+2)*68 + row] = u.z;
        Ut[(c0+c+3)*68 + row] = u.w;
        float4 w = *(const float4*)(Wa + row*64 + c0 + c);
        WaT[(c0+c+0)*68 + row] = w.x;
        WaT[(c0+c+1)*68 + row] = w.y;
        WaT[(c0+c+2)*68 + row] = w.z;
        WaT[(c0+c+3)*68 + row] = w.w;
        float4 x = *(const float4*)(hsrc + c0 + c);
        *(float4*)&Xs[row*68 + c0 + c] = x;
    }
    if (tid < 64){ sGa[tid]=gamma[tid]; sBe[tid]=beta[tid]; sBa[tid]=ba[tid]; }
    __syncthreads();

    float accF[4][4] = {};
    #pragma unroll 8
    for (int t = 0; t < 64; t++){
        float4 af = *(const float4*)&Ug[t*68 + ty*4];
        float4 bf = *(const float4*)&Xs[t*68 + tx*4];
        fma4x4(accF, af, bf);
    }
    #pragma unroll
    for (int i=0;i<4;i++)
        *(float4*)&Fs[(ty*4+i)*68 + tx*4] =
            make_float4(accF[i][0],accF[i][1],accF[i][2],accF[i][3]);
    __syncthreads();

    float ssum=0.f, ssq=0.f;
    #pragma unroll
    for (int c=0;c<16;c+=4){
        float4 f = *(const float4*)&Fs[row*68 + c0 + c];
        ssum += f.x+f.y+f.z+f.w;
        ssq  += f.x*f.x + f.y*f.y + f.z*f.z + f.w*f.w;
    }
    ssum += __shfl_xor_sync(0xffffffffu, ssum, 1);
    ssq  += __shfl_xor_sync(0xffffffffu, ssq , 1);
    ssum += __shfl_xor_sync(0xffffffffu, ssum, 2);
    ssq  += __shfl_xor_sync(0xffffffffu, ssq , 2);
    float mean = ssum * (1.0f/64.0f);
    float var  = ssq  * (1.0f/64.0f) - mean*mean;
    float rstd = rsqrtf(var + 1e-5f);
    #pragma unroll
    for (int c=0;c<16;c+=4){
        float4 f = *(const float4*)&Fs[row*68 + c0 + c];
        Xs[(c0+c+0)*68 + row] = (f.x-mean)*rstd*sGa[c0+c+0] + sBe[c0+c+0];
        Xs[(c0+c+1)*68 + row] = (f.y-mean)*rstd*sGa[c0+c+1] + sBe[c0+c+1];
        Xs[(c0+c+2)*68 + row] = (f.z-mean)*rstd*sGa[c0+c+2] + sBe[c0+c+2];
        Xs[(c0+c+3)*68 + row] = (f.w-mean)*rstd*sGa[c0+c+3] + sBe[c0+c+3];
    }
    __syncthreads();

    float accG[4][4] = {};
    #pragma unroll 8
    for (int t = 0; t < 64; t++){
        float4 af = *(const float4*)&Xs[t*68 + ty*4];
        float4 bf = *(const float4*)&WaT[t*68 + tx*4];
        fma4x4(accG, af, bf);
    }
    #pragma unroll
    for (int i=0;i<4;i++){
        float4 o;
        o.x = accF[i][0] + silu_f(accG[i][0] + sBa[tx*4+0]);
        o.y = accF[i][1] + silu_f(accG[i][1] + sBa[tx*4+1]);
        o.z = accF[i][2] + silu_f(accG[i][2] + sBa[tx*4+2]);
        o.w = accF[i][3] + silu_f(accG[i][3] + sBa[tx*4+3]);
        *(float4*)&Fs[(ty*4+i)*68 + tx*4] = o;
    }
    __syncthreads();

    float accY[4][4] = {};
    #pragma unroll 8
    for (int t = 0; t < 64; t++){
        float4 af = *(const float4*)&Ut[t*68 + ty*4];
        float4 bf = *(const float4*)&Fs[t*68 + tx*4];
        fma4x4(accY, af, bf);
    }
    float* yout = g_y + ((size_t)b*NN + g*64)*NR;
    #pragma unroll
    for (int i=0;i<4;i++)
        *(float4*)(yout + (size_t)(ty*4+i)*NR + tx*4) =
            make_float4(accY[i][0],accY[i][1],accY[i][2],accY[i][3]);
}

// ================= K3: out = (h + y + gather(y,idx1)) @ Wu^T + bu ===========
// tf32 split-3 tensor cores, combine fused into the A-tile load.
// BM=64, BN=384 (full N so A rows are read exactly once), K=64 single pass.
// 8 warps, each 64m x 48n (6 n-tiles).
#define UK_SA 72
#define UK_SMEM ((64*UK_SA + 384*UK_SA + 384)*4)   // 130560 B
__global__ __launch_bounds__(256) void up_kernel(
    const float* __restrict__ Wu, const float* __restrict__ bu,
    float* __restrict__ out)
{
    extern __shared__ float sm[];
    float* As  = sm;                 // [64][72]
    float* Bs  = sm + 64*UK_SA;      // [384][72]
    float* sBu = Bs + 384*UK_SA;     // [384]
    const int tid = threadIdx.x;
    const int wid = tid >> 5, lane = tid & 31;
    const int g = lane >> 2, t4 = lane & 3;
    const int m0 = blockIdx.x * 64;

    // A load: fused h + y + gather(y, idx1), permuted store. 512 items of 8 floats.
    #pragma unroll
    for (int i=0;i<2;i++){
        int item = tid + i*256;
        int row = item >> 3, cc = item & 7;
        int grow = m0 + row;
        int b = grow >> 13, j = grow & (NN-1);
        int src = g_idx[MT + (b<<13) + j];
        const float* hp = g_h + (size_t)grow*NR + cc*8;
        const float* yp = g_y + (size_t)grow*NR + cc*8;
        const float* gp = g_y + ((size_t)((b<<13) + src))*NR + cc*8;
        float4 h0 = *(const float4*)hp,     h1 = *(const float4*)(hp+4);
        float4 y0 = *(const float4*)yp,     y1 = *(const float4*)(yp+4);
        float4 q0 = *(const float4*)gp,     q1 = *(const float4*)(gp+4);
        float4 v0 = make_float4(h0.x+y0.x+q0.x, h0.y+y0.y+q0.y,
                                h0.z+y0.z+q0.z, h0.w+y0.w+q0.w);
        float4 v1 = make_float4(h1.x+y1.x+q1.x, h1.y+y1.y+q1.y,
                                h1.z+y1.z+q1.z, h1.w+y1.w+q1.w);
        float* d = As + row*UK_SA + cc*8;
        *(float4*)(d)   = make_float4(v0.x, v1.x, v0.y, v1.y);
        *(float4*)(d+4) = make_float4(v0.z, v1.z, v0.w, v1.w);
    }
    // B load: Wu[384][64], 3072 items / 256 threads = 12 iters
    #pragma unroll
    for (int i=0;i<12;i++){
        int item = tid + i*256;
        int n = item >> 3, cc = item & 7;
        const float* p = Wu + (size_t)n*NR + cc*8;
        float4 v0 = *(const float4*)p, v1 = *(const float4*)(p+4);
        float* d = Bs + n*UK_SA + cc*8;
        *(float4*)(d)   = make_float4(v0.x, v1.x, v0.y, v1.y);
        *(float4*)(d+4) = make_float4(v0.z, v1.z, v0.w, v1.w);
    }
    for (int i=tid; i<384; i+=256) sBu[i] = bu[i];
    __syncthreads();

    float acc[4][6][4] = {};   // [mt][nt][frag]
    #pragma unroll 2
    for (int c8 = 0; c8 < 8; c8++){
        uint32_t ah[4][4], al[4][4];
        #pragma unroll
        for (int mt=0; mt<4; mt++){
            const float* base = As + (mt*16 + g)*UK_SA + c8*8 + t4*2;
            float2 r0 = *(const float2*)base;
            float2 r8 = *(const float2*)(base + 8*UK_SA);
            tf32_split(r0.x, ah[mt][0], al[mt][0]);
            tf32_split(r8.x, ah[mt][1], al[mt][1]);
            tf32_split(r0.y, ah[mt][2], al[mt][2]);
            tf32_split(r8.y, ah[mt][3], al[mt][3]);
        }
        uint32_t bh[6][2], bl[6][2];
        #pragma unroll
        for (int nt=0; nt<6; nt++){
            const float* base = Bs + (wid*48 + nt*8 + g)*UK_SA + c8*8 + t4*2;
            float2 bv = *(const float2*)base;
            tf32_split(bv.x, bh[nt][0], bl[nt][0]);
            tf32_split(bv.y, bh[nt][1], bl[nt][1]);
        }
        #pragma unroll
        for (int mt=0; mt<4; mt++)
            #pragma unroll
            for (int nt=0; nt<6; nt++){
                mma_tf32(acc[mt][nt], al[mt][0],al[mt][1],al[mt][2],al[mt][3], bh[nt][0],bh[nt][1]);
                mma_tf32(acc[mt][nt], ah[mt][0],ah[mt][1],ah[mt][2],ah[mt][3], bl[nt][0],bl[nt][1]);
                mma_tf32(acc[mt][nt], ah[mt][0],ah[mt][1],ah[mt][2],ah[mt][3], bh[nt][0],bh[nt][1]);
            }
    }

    // epilogue: bias -> out
    #pragma unroll
    for (int mt=0; mt<4; mt++){
        int row = m0 + mt*16 + g;
        #pragma unroll
        for (int nt=0; nt<6; nt++){
            int col = wid*48 + nt*8 + t4*2;
            float b0 = sBu[col], b1 = sBu[col+1];
            float* o = out + (size_t)row*NDIM + col;
            *(float2*)o          = make_float2(acc[mt][nt][0]+b0, acc[mt][nt][1]+b1);
            *(float2*)(o + 8*NDIM) = make_float2(acc[mt][nt][2]+b0, acc[mt][nt][3]+b1);
        }
    }
}

// ---------------- launch ----------------
extern "C" void kernel_launch(void* const* d_in, const int* in_sizes, int n_in,
                              void* d_out, int out_size)
{
    const float* input = (const float*)d_in[0];
    const float* subU  = (const float*)d_in[1];
    const void*  idx   = d_in[2];
    const float* Wd    = (const float*)d_in[3];
    const float* bd    = (const float*)d_in[4];
    const float* Wu    = (const float*)d_in[5];
    const float* bu    = (const float*)d_in[6];
    const float* Wa    = (const float*)d_in[7];
    const float* ba    = (const float*)d_in[8];
    const float* ga    = (const float*)d_in[9];
    const float* be    = (const float*)d_in[10];
    float* out = (float*)d_out;
    (void)in_sizes; (void)n_in; (void)out_size;

    cudaFuncSetAttribute(down_kernel,  cudaFuncAttributeMaxDynamicSharedMemorySize, DK_SMEM);
    cudaFuncSetAttribute(group_kernel, cudaFuncAttributeMaxDynamicSharedMemorySize, K3_SMEM);
    cudaFuncSetAttribute(up_kernel,    cudaFuncAttributeMaxDynamicSharedMemorySize, UK_SMEM);

    probe_idx_kernel<<<1, 128>>>((const unsigned int*)idx);
    convert_idx_kernel<<<(2*MT + 255)/256, 256>>>(idx);
    down_kernel<<<MT/256, 256, DK_SMEM>>>(input, Wd, bd);
    group_kernel<<<NB*NG, 256, K3_SMEM>>>(subU, Wa, ba, ga, be);
    up_kernel<<<MT/64, 256, UK_SMEM>>>(Wu, bu, out);
}

// round 14
// speedup vs baseline: 1.3495x; 1.3493x over previous
#include <cuda_runtime.h>
#include <cstdint>

#define NB 16
#define NN 8192
#define NDIM 384
#define NR 64
#define NG 128
#define MT (NB*NN)

__device__ __align__(256) float g_h[(size_t)MT*NR];
__device__ __align__(256) float g_y[(size_t)MT*NR];
__device__ __align__(256) int   g_idx[2*MT];
__device__ int g_is64;

__device__ __forceinline__ float silu_f(float x){ return x / (1.0f + __expf(-x)); }

// pack pair: low half = even-k, high half = odd-k; hi + residual-lo bf16
__device__ __forceinline__ void bf16pair(float e, float o, uint32_t& hp, uint32_t& lp){
    asm("cvt.rn.bf16x2.f32 %0, %1, %2;" : "=r"(hp) : "f"(o), "f"(e));
    float he = __uint_as_float(hp << 16);
    float ho = __uint_as_float(hp & 0xffff0000u);
    asm("cvt.rn.bf16x2.f32 %0, %1, %2;" : "=r"(lp) : "f"(o - ho), "f"(e - he));
}
__device__ __forceinline__ void bf16split1(float v, unsigned short& hs, unsigned short& ls){
    asm("cvt.rn.bf16.f32 %0, %1;" : "=h"(hs) : "f"(v));
    float hf = __uint_as_float(((uint32_t)hs) << 16);
    asm("cvt.rn.bf16.f32 %0, %1;" : "=h"(ls) : "f"(v - hf));
}
__device__ __forceinline__ void mma_bf16(float (&c)[4],
    uint32_t a0, uint32_t a1, uint32_t a2, uint32_t a3, uint32_t b0, uint32_t b1)
{
    asm volatile("mma.sync.aligned.m16n8k16.row.col.f32.bf16.bf16.f32 "
        "{%0,%1,%2,%3}, {%4,%5,%6,%7}, {%8,%9}, {%0,%1,%2,%3};\n"
        : "+f"(c[0]), "+f"(c[1]), "+f"(c[2]), "+f"(c[3])
        : "r"(a0), "r"(a1), "r"(a2), "r"(a3), "r"(b0), "r"(b1));
}
__device__ __forceinline__ void mma3(float (&c)[4],
    const uint32_t (&aH)[4], const uint32_t (&aL)[4],
    uint32_t bH0, uint32_t bH1, uint32_t bL0, uint32_t bL1)
{
    mma_bf16(c, aL[0],aL[1],aL[2],aL[3], bH0,bH1);
    mma_bf16(c, aH[0],aH[1],aH[2],aH[3], bL0,bL1);
    mma_bf16(c, aH[0],aH[1],aH[2],aH[3], bH0,bH1);
}
// slot permutation within an 8-pair (k16) chunk: pair q -> slot {0,2,4,6,1,3,5,7}[q]
__device__ __forceinline__ int slotof(int q){ return ((q&3)<<1) | (q>>2); }

// 16 consecutive-k floats -> presplit pair-permuted smem chunk
__device__ __forceinline__ void conv_store16(const float4* v, uint32_t* dH, uint32_t* dL){
    uint32_t h[8], l[8];
    #pragma unroll
    for (int j=0;j<4;j++){
        bf16pair(v[j].x, v[j].y, h[2*j],   l[2*j]);
        bf16pair(v[j].z, v[j].w, h[2*j+1], l[2*j+1]);
    }
    *(uint4*)dH     = make_uint4(h[0],h[4],h[1],h[5]);
    *(uint4*)(dH+4) = make_uint4(h[2],h[6],h[3],h[7]);
    *(uint4*)dL     = make_uint4(l[0],l[4],l[1],l[5]);
    *(uint4*)(dL+4) = make_uint4(l[2],l[6],l[3],l[7]);
}
__device__ __forceinline__ void load_afrag(const uint32_t* H, const uint32_t* L, int stride,
                                           uint32_t (&aH)[4], uint32_t (&aL)[4]){
    uint2 h0 = *(const uint2*)H;
    uint2 h1 = *(const uint2*)(H + 8*stride);
    uint2 l0 = *(const uint2*)L;
    uint2 l1 = *(const uint2*)(L + 8*stride);
    aH[0]=h0.x; aH[1]=h1.x; aH[2]=h0.y; aH[3]=h1.y;
    aL[0]=l0.x; aL[1]=l1.x; aL[2]=l0.y; aL[3]=l1.y;
}

__global__ void probe_idx_kernel(const unsigned int* __restrict__ w){
    __shared__ int ok;
    if (threadIdx.x == 0) ok = 1;
    __syncthreads();
    if (w[2*threadIdx.x + 1] != 0u) ok = 0;
    __syncthreads();
    if (threadIdx.x == 0) g_is64 = ok;
}
__global__ void convert_idx_kernel(const void* __restrict__ p){
    int i = blockIdx.x*blockDim.x + threadIdx.x;
    if (i >= 2*MT) return;
    if (g_is64) g_idx[i] = (int)((const long long*)p)[i];
    else        g_idx[i] = ((const int*)p)[i];
}

// ========== K1: h = silu(X @ Wd^T + bd), bf16x3, BM=128 BN=64 BK=32 =========
#define DKP 24
#define DK_SMEM ((128*DKP*2 + 64*DKP*2)*4)
__global__ __launch_bounds__(256) void down_kernel(
    const float* __restrict__ A, const float* __restrict__ Wd,
    const float* __restrict__ bd)
{
    extern __shared__ char smraw[];
    uint32_t* AsH = (uint32_t*)smraw;
    uint32_t* AsL = AsH + 128*DKP;
    uint32_t* BsH = AsL + 128*DKP;
    uint32_t* BsL = BsH + 64*DKP;
    const int tid = threadIdx.x;
    const int wid = tid >> 5, lane = tid & 31;
    const int qr = lane >> 2, t4 = lane & 3;
    const int wm = wid & 3, wn = wid >> 2;          // 4m x 2n warps, warp 32m x 32n
    const int m0 = blockIdx.x * 128;
    const int arow = tid >> 1, achk = tid & 1;
    const bool doB = tid < 128;
    const int brow = tid >> 1, bchk = tid & 1;

    float4 pa[4], pb[4];
    {
        const float* p = A + (size_t)(m0+arow)*NDIM + achk*16;
        #pragma unroll
        for (int j=0;j<4;j++) pa[j] = *(const float4*)(p + j*4);
        if (doB){
            const float* q = Wd + (size_t)brow*NDIM + bchk*16;
            #pragma unroll
            for (int j=0;j<4;j++) pb[j] = *(const float4*)(q + j*4);
        }
    }

    float acc[2][4][4] = {};
    for (int s = 0; s < 12; s++){
        __syncthreads();
        conv_store16(pa, &AsH[arow*DKP + achk*8], &AsL[arow*DKP + achk*8]);
        if (doB) conv_store16(pb, &BsH[brow*DKP + bchk*8], &BsL[brow*DKP + bchk*8]);
        __syncthreads();
        if (s < 11){
            const float* p = A + (size_t)(m0+arow)*NDIM + (s+1)*32 + achk*16;
            #pragma unroll
            for (int j=0;j<4;j++) pa[j] = *(const float4*)(p + j*4);
            if (doB){
                const float* q = Wd + (size_t)brow*NDIM + (s+1)*32 + bchk*16;
                #pragma unroll
                for (int j=0;j<4;j++) pb[j] = *(const float4*)(q + j*4);
            }
        }
        #pragma unroll
        for (int cc = 0; cc < 2; cc++){
            uint32_t aH[2][4], aL[2][4];
            #pragma unroll
            for (int mt=0; mt<2; mt++){
                int off = (wm*32 + mt*16 + qr)*DKP + cc*8 + 2*t4;
                load_afrag(&AsH[off], &AsL[off], DKP, aH[mt], aL[mt]);
            }
            #pragma unroll
            for (int nt=0; nt<4; nt++){
                int n = wn*32 + nt*8 + qr;
                uint2 bh = *(const uint2*)&BsH[n*DKP + cc*8 + 2*t4];
                uint2 bl = *(const uint2*)&BsL[n*DKP + cc*8 + 2*t4];
                #pragma unroll
                for (int mt=0; mt<2; mt++)
                    mma3(acc[mt][nt], aH[mt], aL[mt], bh.x, bh.y, bl.x, bl.y);
            }
        }
    }
    #pragma unroll
    for (int mt=0; mt<2; mt++){
        int row = m0 + wm*32 + mt*16 + qr;
        #pragma unroll
        for (int nt=0; nt<4; nt++){
            int col = wn*32 + nt*8 + 2*t4;
            float b0 = __ldg(bd+col), b1 = __ldg(bd+col+1);
            float* o = g_h + (size_t)row*NR + col;
            *(float2*)o = make_float2(silu_f(acc[mt][nt][0]+b0), silu_f(acc[mt][nt][1]+b1));
            *(float2*)(o + 8*NR) = make_float2(silu_f(acc[mt][nt][2]+b0), silu_f(acc[mt][nt][3]+b1));
        }
    }
}

// ========== K2: fused per-(b,g) branch, bf16x3 mma ==========================
#define GP 40
#define FFS 72
#define GK_SMEM ((8*64*GP + 64*FFS + 3*64)*4)
__global__ __launch_bounds__(256) void group_kernel(
    const float* __restrict__ subU, const float* __restrict__ Wa,
    const float* __restrict__ ba, const float* __restrict__ gamma,
    const float* __restrict__ beta)
{
    extern __shared__ char smraw[];
    uint32_t* b0H = (uint32_t*)smraw;       // Ut, then LN(F)
    uint32_t* b0L = b0H + 64*GP;
    uint32_t* b1H = b0L + 64*GP;            // Xt (gathered)
    uint32_t* b1L = b1H + 64*GP;
    uint32_t* b2H = b1L + 64*GP;            // Ug
    uint32_t* b2L = b2H + 64*GP;
    uint32_t* b3H = b2L + 64*GP;            // Wa, then F2t
    uint32_t* b3L = b3H + 64*GP;
    float*    Ffp = (float*)(b3L + 64*GP);  // [64][72]
    float*    cGa = Ffp + 64*FFS;
    float*    cBe = cGa + 64;
    float*    cBa = cBe + 64;

    const int tid = threadIdx.x;
    const int wid = tid >> 5, lane = tid & 31;
    const int qr = lane >> 2, t4 = lane & 3;
    const int wm = wid & 3, wn = wid >> 2;          // 4m x 2n, warp 16m x 32n
    const int bg = blockIdx.x;
    const int b = bg >> 7, gg = bg & 127;
    const float* U = subU + ((size_t)(16 + b)*128 + gg)*4096;  // sub_U[1][b][gg]

    {   // Ug natural [t][s-pairs]; Wa natural [r][k-pairs]
        int row = tid >> 2, chunk = tid & 3;
        float4 v[4];
        const float* p = U + row*64 + chunk*16;
        #pragma unroll
        for (int j=0;j<4;j++) v[j] = *(const float4*)(p + j*4);
        conv_store16(v, &b2H[row*GP + chunk*8], &b2L[row*GP + chunk*8]);
        const float* q = Wa + row*64 + chunk*16;
        #pragma unroll
        for (int j=0;j<4;j++) v[j] = *(const float4*)(q + j*4);
        conv_store16(v, &b3H[row*GP + chunk*8], &b3L[row*GP + chunk*8]);
    }
    // Ut[s][t-pairs] and gathered Xt[r][t-pairs]
    #pragma unroll
    for (int rep=0; rep<2; rep++){
        int item = tid + rep*256;
        int tp = item & 31, sc = item >> 5;   // t-pair, column quad
        int t0 = 2*tp;
        int sl = (tp>>3)*8 + slotof(tp&7);
        float4 a0 = *(const float4*)(U + t0*64 + sc*4);
        float4 a1 = *(const float4*)(U + (t0+1)*64 + sc*4);
        float ea[4] = {a0.x,a0.y,a0.z,a0.w};
        float eo[4] = {a1.x,a1.y,a1.z,a1.w};
        #pragma unroll
        for (int jj=0;jj<4;jj++){
            uint32_t hp, lp;
            bf16pair(ea[jj], eo[jj], hp, lp);
            int s = sc*4 + jj;
            b0H[s*GP + sl] = hp; b0L[s*GP + sl] = lp;
        }
        int src0 = g_idx[b*NN + gg*64 + t0];
        int src1 = g_idx[b*NN + gg*64 + t0 + 1];
        float4 x0 = *(const float4*)(g_h + ((size_t)b*NN + src0)*NR + sc*4);
        float4 x1 = *(const float4*)(g_h + ((size_t)b*NN + src1)*NR + sc*4);
        float xa[4] = {x0.x,x0.y,x0.z,x0.w};
        float xb[4] = {x1.x,x1.y,x1.z,x1.w};
        #pragma unroll
        for (int jj=0;jj<4;jj++){
            uint32_t hp, lp;
            bf16pair(xa[jj], xb[jj], hp, lp);
            int s = sc*4 + jj;
            b1H[s*GP + sl] = hp; b1L[s*GP + sl] = lp;
        }
    }
    if (tid < 64){ cGa[tid]=gamma[tid]; cBe[tid]=beta[tid]; cBa[tid]=ba[tid]; }
    __syncthreads();

    // G1: F[s][r] = sum_t U[t][s] X[t][r]   (A=Ut b0, B=Xt b1)
    float accF[4][4] = {};
    #pragma unroll
    for (int cc=0; cc<4; cc++){
        uint32_t aH[4], aL[4];
        int offa = (wm*16 + qr)*GP + cc*8 + 2*t4;
        load_afrag(&b0H[offa], &b0L[offa], GP, aH, aL);
        #pragma unroll
        for (int nt=0; nt<4; nt++){
            int n = wn*32 + nt*8 + qr;
            uint2 bh = *(const uint2*)&b1H[n*GP + cc*8 + 2*t4];
            uint2 bl = *(const uint2*)&b1L[n*GP + cc*8 + 2*t4];
            mma3(accF[nt], aH, aL, bh.x, bh.y, bl.x, bl.y);
        }
    }
    __syncthreads();
    #pragma unroll
    for (int nt=0; nt<4; nt++){
        int col = wn*32 + nt*8 + 2*t4;
        *(float2*)&Ffp[(wm*16+qr)*FFS + col]   = make_float2(accF[nt][0], accF[nt][1]);
        *(float2*)&Ffp[(wm*16+qr+8)*FFS + col] = make_float2(accF[nt][2], accF[nt][3]);
    }
    __syncthreads();

    // LN over r per s-row; presplit natural into b0 (Ut dead)
    {
        int row = tid >> 2, ch = tid & 3;
        float f[16];
        #pragma unroll
        for (int j=0;j<4;j++){
            float4 v = *(const float4*)&Ffp[row*FFS + ch*16 + j*4];
            f[4*j]=v.x; f[4*j+1]=v.y; f[4*j+2]=v.z; f[4*j+3]=v.w;
        }
        float ssum=0.f, ssq=0.f;
        #pragma unroll
        for (int j=0;j<16;j++){ ssum += f[j]; ssq += f[j]*f[j]; }
        ssum += __shfl_xor_sync(0xffffffffu, ssum, 1);
        ssq  += __shfl_xor_sync(0xffffffffu, ssq , 1);
        ssum += __shfl_xor_sync(0xffffffffu, ssum, 2);
        ssq  += __shfl_xor_sync(0xffffffffu, ssq , 2);
        float mean = ssum * (1.0f/64.0f);
        float var  = ssq  * (1.0f/64.0f) - mean*mean;
        float rstd = rsqrtf(var + 1e-5f);
        uint32_t h[8], l[8];
        #pragma unroll
        for (int q=0;q<8;q++){
            int k0 = ch*16 + 2*q;
            float e = (f[2*q]  -mean)*rstd*cGa[k0]   + cBe[k0];
            float o = (f[2*q+1]-mean)*rstd*cGa[k0+1] + cBe[k0+1];
            bf16pair(e, o, h[q], l[q]);
        }
        uint32_t* dH = &b0H[row*GP + ch*8];
        uint32_t* dL = &b0L[row*GP + ch*8];
        *(uint4*)dH     = make_uint4(h[0],h[4],h[1],h[5]);
        *(uint4*)(dH+4) = make_uint4(h[2],h[6],h[3],h[7]);
        *(uint4*)dL     = make_uint4(l[0],l[4],l[1],l[5]);
        *(uint4*)(dL+4) = make_uint4(l[2],l[6],l[3],l[7]);
    }
    __syncthreads();

    // G2: G[s][r] = sum_k LN[s][k] Wa[r][k]   (A=b0, B=b3)
    float accG[4][4] = {};
    #pragma unroll
    for (int cc=0; cc<4; cc++){
        uint32_t aH[4], aL[4];
        int offa = (wm*16 + qr)*GP + cc*8 + 2*t4;
        load_afrag(&b0H[offa], &b0L[offa], GP, aH, aL);
        #pragma unroll
        for (int nt=0; nt<4; nt++){
            int n = wn*32 + nt*8 + qr;
            uint2 bh = *(const uint2*)&b3H[n*GP + cc*8 + 2*t4];
            uint2 bl = *(const uint2*)&b3L[n*GP + cc*8 + 2*t4];
            mma3(accG[nt], aH, aL, bh.x, bh.y, bl.x, bl.y);
        }
    }
    __syncthreads();   // everyone done reading Wa from b3

    // F2 = F + silu(G + ba) -> transposed presplit into b3: b3[r][s-pairs]
    #pragma unroll
    for (int nt=0; nt<4; nt++){
        int colb = wn*32 + nt*8 + 2*t4;
        #pragma unroll
        for (int c=0; c<4; c++){
            int srow = wm*16 + qr + (c>>1)*8;
            int col  = colb + (c&1);
            float v = accF[nt][c] + silu_f(accG[nt][c] + cBa[col]);
            int sp = srow >> 1, half = srow & 1;
            int sl = (sp>>3)*8 + slotof(sp&7);
            unsigned short hs, ls;
            bf16split1(v, hs, ls);
            ((unsigned short*)(b3H + col*GP + sl))[half] = hs;
            ((unsigned short*)(b3L + col*GP + sl))[half] = ls;
        }
    }
    __syncthreads();

    // G3: Y[s][r] = sum_t U[s][t] F2[t][r]   (A=Ug b2, B=F2t b3)
    float accY[4][4] = {};
    #pragma unroll
    for (int cc=0; cc<4; cc++){
        uint32_t aH[4], aL[4];
        int offa = (wm*16 + qr)*GP + cc*8 + 2*t4;
        load_afrag(&b2H[offa], &b2L[offa], GP, aH, aL);
        #pragma unroll
        for (int nt=0; nt<4; nt++){
            int n = wn*32 + nt*8 + qr;
            uint2 bh = *(const uint2*)&b3H[n*GP + cc*8 + 2*t4];
            uint2 bl = *(const uint2*)&b3L[n*GP + cc*8 + 2*t4];
            mma3(accY[nt], aH, aL, bh.x, bh.y, bl.x, bl.y);
        }
    }
    float* yout = g_y + ((size_t)b*NN + gg*64)*NR;
    #pragma unroll
    for (int nt=0; nt<4; nt++){
        int col = wn*32 + nt*8 + 2*t4;
        *(float2*)(yout + (size_t)(wm*16+qr)*NR + col)   = make_float2(accY[nt][0], accY[nt][1]);
        *(float2*)(yout + (size_t)(wm*16+qr+8)*NR + col) = make_float2(accY[nt][2], accY[nt][3]);
    }
}

// ========== K3: out = (h + y + gather(y,idx1)) @ Wu^T + bu ==================
// BM=64, BN=384, K=64. 512 thr = 16 warps (4m x 4n), warp 16m x 96n.
// NOTE: A presplit stride UKP=40 uint32; B fp32 stride UKB=72 floats (own stride!).
#define UKP 40
#define UKB 72
#define UK_SMEM ((64*UKP*2 + 384*UKB + 384)*4)
__global__ __launch_bounds__(512) void up_kernel(
    const float* __restrict__ Wu, const float* __restrict__ bu,
    float* __restrict__ out)
{
    extern __shared__ char smraw[];
    uint32_t* AsH = (uint32_t*)smraw;
    uint32_t* AsL = AsH + 64*UKP;
    float*    Bsf = (float*)(AsL + 64*UKP);   // [384][UKB] fp32
    float*    sBu = Bsf + 384*UKB;
    const int tid = threadIdx.x;
    const int wid = tid >> 5, lane = tid & 31;
    const int qr = lane >> 2, t4 = lane & 3;
    const int wm = wid & 3, wn = wid >> 2;
    const int m0 = blockIdx.x * 64;

    if (tid < 256){   // A: fused combine, presplit
        int row = tid >> 2, chunk = tid & 3;
        int grow = m0 + row;
        int b = grow >> 13, j = grow & (NN-1);
        int src = g_idx[MT + (b<<13) + j];
        const float* hp = g_h + (size_t)grow*NR + chunk*16;
        const float* yp = g_y + (size_t)grow*NR + chunk*16;
        const float* gp = g_y + ((size_t)((b<<13) + src))*NR + chunk*16;
        float4 v[4];
        #pragma unroll
        for (int j4=0;j4<4;j4++){
            float4 a = *(const float4*)(hp + j4*4);
            float4 c = *(const float4*)(yp + j4*4);
            float4 d = *(const float4*)(gp + j4*4);
            v[j4] = make_float4(a.x+c.x+d.x, a.y+c.y+d.y, a.z+c.z+d.z, a.w+c.w+d.w);
        }
        conv_store16(v, &AsH[row*UKP + chunk*8], &AsL[row*UKP + chunk*8]);
    }
    #pragma unroll
    for (int i=0;i<12;i++){
        int f = tid + i*512;
        int n = f >> 4, c = (f & 15)*4;
        *(float4*)&Bsf[n*UKB + c] = *(const float4*)(Wu + (size_t)n*NR + c);
    }
    if (tid < 384) sBu[tid] = bu[tid];
    __syncthreads();

    float acc[12][4] = {};
    #pragma unroll
    for (int cc=0; cc<4; cc++){
        uint32_t aH[4], aL[4];
        int offa = (wm*16 + qr)*UKP + cc*8 + 2*t4;
        load_afrag(&AsH[offa], &AsL[offa], UKP, aH, aL);
        #pragma unroll
        for (int nt=0; nt<12; nt++){
            int n = wn*96 + nt*8 + qr;
            float2 f0 = *(const float2*)&Bsf[n*UKB + cc*16 + 2*t4];
            float2 f1 = *(const float2*)&Bsf[n*UKB + cc*16 + 2*t4 + 8];
            uint32_t bh0,bl0,bh1,bl1;
            bf16pair(f0.x, f0.y, bh0, bl0);
            bf16pair(f1.x, f1.y, bh1, bl1);
            mma3(acc[nt], aH, aL, bh0, bh1, bl0, bl1);
        }
    }
    #pragma unroll
    for (int nt=0; nt<12; nt++){
        int col = wn*96 + nt*8 + 2*t4;
        float b0 = sBu[col], b1 = sBu[col+1];
        int row = m0 + wm*16 + qr;
        float* o = out + (size_t)row*NDIM + col;
        *(float2*)o            = make_float2(acc[nt][0]+b0, acc[nt][1]+b1);
        *(float2*)(o + 8*NDIM) = make_float2(acc[nt][2]+b0, acc[nt][3]+b1);
    }
}

extern "C" void kernel_launch(void* const* d_in, const int* in_sizes, int n_in,
                              void* d_out, int out_size)
{
    const float* input = (const float*)d_in[0];
    const float* subU  = (const float*)d_in[1];
    const void*  idx   = d_in[2];
    const float* Wd    = (const float*)d_in[3];
    const float* bd    = (const float*)d_in[4];
    const float* Wu    = (const float*)d_in[5];
    const float* bu    = (const float*)d_in[6];
    const float* Wa    = (const float*)d_in[7];
    const float* ba    = (const float*)d_in[8];
    const float* ga    = (const float*)d_in[9];
    const float* be    = (const float*)d_in[10];
    float* out = (float*)d_out;
    (void)in_sizes; (void)n_in; (void)out_size;

    cudaFuncSetAttribute(down_kernel,  cudaFuncAttributeMaxDynamicSharedMemorySize, DK_SMEM);
    cudaFuncSetAttribute(group_kernel, cudaFuncAttributeMaxDynamicSharedMemorySize, GK_SMEM);
    cudaFuncSetAttribute(up_kernel,    cudaFuncAttributeMaxDynamicSharedMemorySize, UK_SMEM);

    probe_idx_kernel<<<1, 128>>>((const unsigned int*)idx);
    convert_idx_kernel<<<(2*MT + 255)/256, 256>>>(idx);
    down_kernel<<<MT/128, 256, DK_SMEM>>>(input, Wd, bd);
    group_kernel<<<NB*NG, 256, GK_SMEM>>>(subU, Wa, ba, ga, be);
    up_kernel<<<MT/64, 512, UK_SMEM>>>(Wu, bu, out);
}

// round 15
// speedup vs baseline: 1.3915x; 1.0311x over previous
#include <cuda_runtime.h>
#include <cstdint>

#define NB 16
#define NN 8192
#define NDIM 384
#define NR 64
#define NG 128
#define MT (NB*NN)

__device__ __align__(256) float g_h[(size_t)MT*NR];
__device__ __align__(256) float g_y[(size_t)MT*NR];
__device__ __align__(256) int   g_idx[2*MT];
__device__ int g_is64;

__device__ __forceinline__ float silu_f(float x){ return x / (1.0f + __expf(-x)); }

// pack pair: low half = even-k, high half = odd-k; hi + residual-lo bf16
__device__ __forceinline__ void bf16pair(float e, float o, uint32_t& hp, uint32_t& lp){
    asm("cvt.rn.bf16x2.f32 %0, %1, %2;" : "=r"(hp) : "f"(o), "f"(e));
    float he = __uint_as_float(hp << 16);
    float ho = __uint_as_float(hp & 0xffff0000u);
    asm("cvt.rn.bf16x2.f32 %0, %1, %2;" : "=r"(lp) : "f"(o - ho), "f"(e - he));
}
__device__ __forceinline__ void bf16split1(float v, unsigned short& hs, unsigned short& ls){
    asm("cvt.rn.bf16.f32 %0, %1;" : "=h"(hs) : "f"(v));
    float hf = __uint_as_float(((uint32_t)hs) << 16);
    asm("cvt.rn.bf16.f32 %0, %1;" : "=h"(ls) : "f"(v - hf));
}
__device__ __forceinline__ void mma_bf16(float (&c)[4],
    uint32_t a0, uint32_t a1, uint32_t a2, uint32_t a3, uint32_t b0, uint32_t b1)
{
    asm volatile("mma.sync.aligned.m16n8k16.row.col.f32.bf16.bf16.f32 "
        "{%0,%1,%2,%3}, {%4,%5,%6,%7}, {%8,%9}, {%0,%1,%2,%3};\n"
        : "+f"(c[0]), "+f"(c[1]), "+f"(c[2]), "+f"(c[3])
        : "r"(a0), "r"(a1), "r"(a2), "r"(a3), "r"(b0), "r"(b1));
}
__device__ __forceinline__ void mma3(float (&c)[4],
    const uint32_t (&aH)[4], const uint32_t (&aL)[4],
    uint32_t bH0, uint32_t bH1, uint32_t bL0, uint32_t bL1)
{
    mma_bf16(c, aL[0],aL[1],aL[2],aL[3], bH0,bH1);
    mma_bf16(c, aH[0],aH[1],aH[2],aH[3], bL0,bL1);
    mma_bf16(c, aH[0],aH[1],aH[2],aH[3], bH0,bH1);
}
// slot permutation within an 8-pair (k16) chunk: pair q -> slot {0,2,4,6,1,3,5,7}[q]
__device__ __forceinline__ int slotof(int q){ return ((q&3)<<1) | (q>>2); }

// 16 consecutive-k floats -> presplit pair-permuted smem chunk
__device__ __forceinline__ void conv_store16(const float4* v, uint32_t* dH, uint32_t* dL){
    uint32_t h[8], l[8];
    #pragma unroll
    for (int j=0;j<4;j++){
        bf16pair(v[j].x, v[j].y, h[2*j],   l[2*j]);
        bf16pair(v[j].z, v[j].w, h[2*j+1], l[2*j+1]);
    }
    *(uint4*)dH     = make_uint4(h[0],h[4],h[1],h[5]);
    *(uint4*)(dH+4) = make_uint4(h[2],h[6],h[3],h[7]);
    *(uint4*)dL     = make_uint4(l[0],l[4],l[1],l[5]);
    *(uint4*)(dL+4) = make_uint4(l[2],l[6],l[3],l[7]);
}
__device__ __forceinline__ void load_afrag(const uint32_t* H, const uint32_t* L, int stride,
                                           uint32_t (&aH)[4], uint32_t (&aL)[4]){
    uint2 h0 = *(const uint2*)H;
    uint2 h1 = *(const uint2*)(H + 8*stride);
    uint2 l0 = *(const uint2*)L;
    uint2 l1 = *(const uint2*)(L + 8*stride);
    aH[0]=h0.x; aH[1]=h1.x; aH[2]=h0.y; aH[3]=h1.y;
    aL[0]=l0.x; aL[1]=l1.x; aL[2]=l0.y; aL[3]=l1.y;
}

__global__ void probe_idx_kernel(const unsigned int* __restrict__ w){
    __shared__ int ok;
    if (threadIdx.x == 0) ok = 1;
    __syncthreads();
    if (w[2*threadIdx.x + 1] != 0u) ok = 0;
    __syncthreads();
    if (threadIdx.x == 0) g_is64 = ok;
}
__global__ void convert_idx_kernel(const void* __restrict__ p){
    int i = blockIdx.x*blockDim.x + threadIdx.x;
    if (i >= 2*MT) return;
    if (g_is64) g_idx[i] = (int)((const long long*)p)[i];
    else        g_idx[i] = ((const int*)p)[i];
}

// ========== K1: h = silu(X @ Wd^T + bd), bf16x3, BM=128 BN=64 BK=32 =========
// Double-buffered stages: one __syncthreads per stage.
#define DKP 24
#define DK_BUF (128*DKP*2 + 64*DKP*2)           // 9216 words per buffer
#define DK_SMEM (2*DK_BUF*4)                    // 73728 B
__global__ __launch_bounds__(256) void down_kernel(
    const float* __restrict__ A, const float* __restrict__ Wd,
    const float* __restrict__ bd)
{
    extern __shared__ char smraw[];
    uint32_t* base = (uint32_t*)smraw;
    const int tid = threadIdx.x;
    const int wid = tid >> 5, lane = tid & 31;
    const int qr = lane >> 2, t4 = lane & 3;
    const int wm = wid & 3, wn = wid >> 2;          // 4m x 2n warps, warp 32m x 32n
    const int m0 = blockIdx.x * 128;
    const int arow = tid >> 1, achk = tid & 1;
    const bool doB = tid < 128;
    const int brow = tid >> 1, bchk = tid & 1;

    float4 pa[4], pb[4];
    {
        const float* p = A + (size_t)(m0+arow)*NDIM + achk*16;
        #pragma unroll
        for (int j=0;j<4;j++) pa[j] = *(const float4*)(p + j*4);
        if (doB){
            const float* q = Wd + (size_t)brow*NDIM + bchk*16;
            #pragma unroll
            for (int j=0;j<4;j++) pb[j] = *(const float4*)(q + j*4);
        }
    }
    {   // store stage 0 into buffer 0
        uint32_t* AsH = base;
        uint32_t* AsL = AsH + 128*DKP;
        uint32_t* BsH = AsL + 128*DKP;
        uint32_t* BsL = BsH + 64*DKP;
        conv_store16(pa, &AsH[arow*DKP + achk*8], &AsL[arow*DKP + achk*8]);
        if (doB) conv_store16(pb, &BsH[brow*DKP + bchk*8], &BsL[brow*DKP + bchk*8]);
    }
    __syncthreads();

    float acc[2][4][4] = {};
    for (int s = 0; s < 12; s++){
        uint32_t* cb  = base + (s&1)*DK_BUF;
        uint32_t* AsH = cb;
        uint32_t* AsL = AsH + 128*DKP;
        uint32_t* BsH = AsL + 128*DKP;
        uint32_t* BsL = BsH + 64*DKP;

        if (s < 11){   // prefetch next stage into regs
            const float* p = A + (size_t)(m0+arow)*NDIM + (s+1)*32 + achk*16;
            #pragma unroll
            for (int j=0;j<4;j++) pa[j] = *(const float4*)(p + j*4);
            if (doB){
                const float* q = Wd + (size_t)brow*NDIM + (s+1)*32 + bchk*16;
                #pragma unroll
                for (int j=0;j<4;j++) pb[j] = *(const float4*)(q + j*4);
            }
        }

        #pragma unroll
        for (int cc = 0; cc < 2; cc++){
            uint32_t aH[2][4], aL[2][4];
            #pragma unroll
            for (int mt=0; mt<2; mt++){
                int off = (wm*32 + mt*16 + qr)*DKP + cc*8 + 2*t4;
                load_afrag(&AsH[off], &AsL[off], DKP, aH[mt], aL[mt]);
            }
            #pragma unroll
            for (int nt=0; nt<4; nt++){
                int n = wn*32 + nt*8 + qr;
                uint2 bh = *(const uint2*)&BsH[n*DKP + cc*8 + 2*t4];
                uint2 bl = *(const uint2*)&BsL[n*DKP + cc*8 + 2*t4];
                #pragma unroll
                for (int mt=0; mt<2; mt++)
                    mma3(acc[mt][nt], aH[mt], aL[mt], bh.x, bh.y, bl.x, bl.y);
            }
        }

        if (s < 11){   // convert+store next stage into the other buffer
            uint32_t* nb  = base + ((s+1)&1)*DK_BUF;
            uint32_t* nAsH = nb;
            uint32_t* nAsL = nAsH + 128*DKP;
            uint32_t* nBsH = nAsL + 128*DKP;
            uint32_t* nBsL = nBsH + 64*DKP;
            conv_store16(pa, &nAsH[arow*DKP + achk*8], &nAsL[arow*DKP + achk*8]);
            if (doB) conv_store16(pb, &nBsH[brow*DKP + bchk*8], &nBsL[brow*DKP + bchk*8]);
            __syncthreads();
        }
    }

    #pragma unroll
    for (int mt=0; mt<2; mt++){
        int row = m0 + wm*32 + mt*16 + qr;
        #pragma unroll
        for (int nt=0; nt<4; nt++){
            int col = wn*32 + nt*8 + 2*t4;
            float b0 = __ldg(bd+col), b1 = __ldg(bd+col+1);
            float* o = g_h + (size_t)row*NR + col;
            *(float2*)o = make_float2(silu_f(acc[mt][nt][0]+b0), silu_f(acc[mt][nt][1]+b1));
            *(float2*)(o + 8*NR) = make_float2(silu_f(acc[mt][nt][2]+b0), silu_f(acc[mt][nt][3]+b1));
        }
    }
}

// ========== K2: fused per-(b,g) branch, bf16x3 mma ==========================
// Ffp overlaid on b1 (Xt dead after G1): smem 101KB -> 82.7KB => 2 blocks/SM.
#define GP 40
#define FFS 72
#define GK_SMEM ((8*64*GP + 3*64)*4)   // 82688 B
__global__ __launch_bounds__(256) void group_kernel(
    const float* __restrict__ subU, const float* __restrict__ Wa,
    const float* __restrict__ ba, const float* __restrict__ gamma,
    const float* __restrict__ beta)
{
    extern __shared__ char smraw[];
    uint32_t* b0H = (uint32_t*)smraw;       // Ut, then LN(F)
    uint32_t* b0L = b0H + 64*GP;
    uint32_t* b1H = b0L + 64*GP;            // Xt (gathered); Ffp overlays after G1
    uint32_t* b1L = b1H + 64*GP;
    uint32_t* b2H = b1L + 64*GP;            // Ug
    uint32_t* b2L = b2H + 64*GP;
    uint32_t* b3H = b2L + 64*GP;            // Wa, then F2t
    uint32_t* b3L = b3H + 64*GP;
    float*    cGa = (float*)(b3L + 64*GP);
    float*    cBe = cGa + 64;
    float*    cBa = cBe + 64;
    float*    Ffp = (float*)b1H;            // [64][72] overlay (needs 18432 <= 20480 B)

    const int tid = threadIdx.x;
    const int wid = tid >> 5, lane = tid & 31;
    const int qr = lane >> 2, t4 = lane & 3;
    const int wm = wid & 3, wn = wid >> 2;          // 4m x 2n, warp 16m x 32n
    const int bg = blockIdx.x;
    const int b = bg >> 7, gg = bg & 127;
    const float* U = subU + ((size_t)(16 + b)*128 + gg)*4096;  // sub_U[1][b][gg]

    {   // Ug natural [t][s-pairs]; Wa natural [r][k-pairs]
        int row = tid >> 2, chunk = tid & 3;
        float4 v[4];
        const float* p = U + row*64 + chunk*16;
        #pragma unroll
        for (int j=0;j<4;j++) v[j] = *(const float4*)(p + j*4);
        conv_store16(v, &b2H[row*GP + chunk*8], &b2L[row*GP + chunk*8]);
        const float* q = Wa + row*64 + chunk*16;
        #pragma unroll
        for (int j=0;j<4;j++) v[j] = *(const float4*)(q + j*4);
        conv_store16(v, &b3H[row*GP + chunk*8], &b3L[row*GP + chunk*8]);
    }
    // Ut[s][t-pairs] and gathered Xt[r][t-pairs]
    #pragma unroll
    for (int rep=0; rep<2; rep++){
        int item = tid + rep*256;
        int tp = item & 31, sc = item >> 5;   // t-pair, column quad
        int t0 = 2*tp;
        int sl = (tp>>3)*8 + slotof(tp&7);
        float4 a0 = *(const float4*)(U + t0*64 + sc*4);
        float4 a1 = *(const float4*)(U + (t0+1)*64 + sc*4);
        float ea[4] = {a0.x,a0.y,a0.z,a0.w};
        float eo[4] = {a1.x,a1.y,a1.z,a1.w};
        #pragma unroll
        for (int jj=0;jj<4;jj++){
            uint32_t hp, lp;
            bf16pair(ea[jj], eo[jj], hp, lp);
            int s = sc*4 + jj;
            b0H[s*GP + sl] = hp; b0L[s*GP + sl] = lp;
        }
        int src0 = g_idx[b*NN + gg*64 + t0];
        int src1 = g_idx[b*NN + gg*64 + t0 + 1];
        float4 x0 = *(const float4*)(g_h + ((size_t)b*NN + src0)*NR + sc*4);
        float4 x1 = *(const float4*)(g_h + ((size_t)b*NN + src1)*NR + sc*4);
        float xa[4] = {x0.x,x0.y,x0.z,x0.w};
        float xb[4] = {x1.x,x1.y,x1.z,x1.w};
        #pragma unroll
        for (int jj=0;jj<4;jj++){
            uint32_t hp, lp;
            bf16pair(xa[jj], xb[jj], hp, lp);
            int s = sc*4 + jj;
            b1H[s*GP + sl] = hp; b1L[s*GP + sl] = lp;
        }
    }
    if (tid < 64){ cGa[tid]=gamma[tid]; cBe[tid]=beta[tid]; cBa[tid]=ba[tid]; }
    __syncthreads();

    // G1: F[s][r] = sum_t U[t][s] X[t][r]   (A=Ut b0, B=Xt b1)
    float accF[4][4] = {};
    #pragma unroll
    for (int cc=0; cc<4; cc++){
        uint32_t aH[4], aL[4];
        int offa = (wm*16 + qr)*GP + cc*8 + 2*t4;
        load_afrag(&b0H[offa], &b0L[offa], GP, aH, aL);
        #pragma unroll
        for (int nt=0; nt<4; nt++){
            int n = wn*32 + nt*8 + qr;
            uint2 bh = *(const uint2*)&b1H[n*GP + cc*8 + 2*t4];
            uint2 bl = *(const uint2*)&b1L[n*GP + cc*8 + 2*t4];
            mma3(accF[nt], aH, aL, bh.x, bh.y, bl.x, bl.y);
        }
    }
    __syncthreads();   // Xt dead; Ffp may overwrite b1
    #pragma unroll
    for (int nt=0; nt<4; nt++){
        int col = wn*32 + nt*8 + 2*t4;
        *(float2*)&Ffp[(wm*16+qr)*FFS + col]   = make_float2(accF[nt][0], accF[nt][1]);
        *(float2*)&Ffp[(wm*16+qr+8)*FFS + col] = make_float2(accF[nt][2], accF[nt][3]);
    }
    __syncthreads();

    // LN over r per s-row; presplit natural into b0 (Ut dead)
    {
        int row = tid >> 2, ch = tid & 3;
        float f[16];
        #pragma unroll
        for (int j=0;j<4;j++){
            float4 v = *(const float4*)&Ffp[row*FFS + ch*16 + j*4];
            f[4*j]=v.x; f[4*j+1]=v.y; f[4*j+2]=v.z; f[4*j+3]=v.w;
        }
        float ssum=0.f, ssq=0.f;
        #pragma unroll
        for (int j=0;j<16;j++){ ssum += f[j]; ssq += f[j]*f[j]; }
        ssum += __shfl_xor_sync(0xffffffffu, ssum, 1);
        ssq  += __shfl_xor_sync(0xffffffffu, ssq , 1);
        ssum += __shfl_xor_sync(0xffffffffu, ssum, 2);
        ssq  += __shfl_xor_sync(0xffffffffu, ssq , 2);
        float mean = ssum * (1.0f/64.0f);
        float var  = ssq  * (1.0f/64.0f) - mean*mean;
        float rstd = rsqrtf(var + 1e-5f);
        uint32_t h[8], l[8];
        #pragma unroll
        for (int q=0;q<8;q++){
            int k0 = ch*16 + 2*q;
            float e = (f[2*q]  -mean)*rstd*cGa[k0]   + cBe[k0];
            float o = (f[2*q+1]-mean)*rstd*cGa[k0+1] + cBe[k0+1];
            bf16pair(e, o, h[q], l[q]);
        }
        uint32_t* dH = &b0H[row*GP + ch*8];
        uint32_t* dL = &b0L[row*GP + ch*8];
        *(uint4*)dH     = make_uint4(h[0],h[4],h[1],h[5]);
        *(uint4*)(dH+4) = make_uint4(h[2],h[6],h[3],h[7]);
        *(uint4*)dL     = make_uint4(l[0],l[4],l[1],l[5]);
        *(uint4*)(dL+4) = make_uint4(l[2],l[6],l[3],l[7]);
    }
    __syncthreads();

    // G2: G[s][r] = sum_k LN[s][k] Wa[r][k]   (A=b0, B=b3)
    float accG[4][4] = {};
    #pragma unroll
    for (int cc=0; cc<4; cc++){
        uint32_t aH[4], aL[4];
        int offa = (wm*16 + qr)*GP + cc*8 + 2*t4;
        load_afrag(&b0H[offa], &b0L[offa], GP, aH, aL);
        #pragma unroll
        for (int nt=0; nt<4; nt++){
            int n = wn*32 + nt*8 + qr;
            uint2 bh = *(const uint2*)&b3H[n*GP + cc*8 + 2*t4];
            uint2 bl = *(const uint2*)&b3L[n*GP + cc*8 + 2*t4];
            mma3(accG[nt], aH, aL, bh.x, bh.y, bl.x, bl.y);
        }
    }
    __syncthreads();   // everyone done reading Wa from b3

    // F2 = F + silu(G + ba) -> transposed presplit into b3: b3[r][s-pairs]
    #pragma unroll
    for (int nt=0; nt<4; nt++){
        int colb = wn*32 + nt*8 + 2*t4;
        #pragma unroll
        for (int c=0; c<4; c++){
            int srow = wm*16 + qr + (c>>1)*8;
            int col  = colb + (c&1);
            float v = accF[nt][c] + silu_f(accG[nt][c] + cBa[col]);
            int sp = srow >> 1, half = srow & 1;
            int sl = (sp>>3)*8 + slotof(sp&7);
            unsigned short hs, ls;
            bf16split1(v, hs, ls);
            ((unsigned short*)(b3H + col*GP + sl))[half] = hs;
            ((unsigned short*)(b3L + col*GP + sl))[half] = ls;
        }
    }
    __syncthreads();

    // G3: Y[s][r] = sum_t U[s][t] F2[t][r]   (A=Ug b2, B=F2t b3)
    float accY[4][4] = {};
    #pragma unroll
    for (int cc=0; cc<4; cc++){
        uint32_t aH[4], aL[4];
        int offa = (wm*16 + qr)*GP + cc*8 + 2*t4;
        load_afrag(&b2H[offa], &b2L[offa], GP, aH, aL);
        #pragma unroll
        for (int nt=0; nt<4; nt++){
            int n = wn*32 + nt*8 + qr;
            uint2 bh = *(const uint2*)&b3H[n*GP + cc*8 + 2*t4];
            uint2 bl = *(const uint2*)&b3L[n*GP + cc*8 + 2*t4];
            mma3(accY[nt], aH, aL, bh.x, bh.y, bl.x, bl.y);
        }
    }
    float* yout = g_y + ((size_t)b*NN + gg*64)*NR;
    #pragma unroll
    for (int nt=0; nt<4; nt++){
        int col = wn*32 + nt*8 + 2*t4;
        *(float2*)(yout + (size_t)(wm*16+qr)*NR + col)   = make_float2(accY[nt][0], accY[nt][1]);
        *(float2*)(yout + (size_t)(wm*16+qr+8)*NR + col) = make_float2(accY[nt][2], accY[nt][3]);
    }
}

// ========== K3: out = (h + y + gather(y,idx1)) @ Wu^T + bu ==================
// BM=64, BN=384, K=64. 512 thr = 16 warps (4m x 4n), warp 16m x 96n.
// Both A and B presplit bf16 H/L in smem (B converted once, not per warp).
#define UKP 40
#define UK_SMEM ((64*UKP*2 + 384*UKP*2 + 384)*4)   // 144896 B
__global__ __launch_bounds__(512) void up_kernel(
    const float* __restrict__ Wu, const float* __restrict__ bu,
    float* __restrict__ out)
{
    extern __shared__ char smraw[];
    uint32_t* AsH = (uint32_t*)smraw;
    uint32_t* AsL = AsH + 64*UKP;
    uint32_t* BsH = AsL + 64*UKP;
    uint32_t* BsL = BsH + 384*UKP;
    float*    sBu = (float*)(BsL + 384*UKP);
    const int tid = threadIdx.x;
    const int wid = tid >> 5, lane = tid & 31;
    const int qr = lane >> 2, t4 = lane & 3;
    const int wm = wid & 3, wn = wid >> 2;
    const int m0 = blockIdx.x * 64;

    if (tid < 256){   // A: fused combine, presplit
        int row = tid >> 2, chunk = tid & 3;
        int grow = m0 + row;
        int b = grow >> 13, j = grow & (NN-1);
        int src = g_idx[MT + (b<<13) + j];
        const float* hp = g_h + (size_t)grow*NR + chunk*16;
        const float* yp = g_y + (size_t)grow*NR + chunk*16;
        const float* gp = g_y + ((size_t)((b<<13) + src))*NR + chunk*16;
        float4 v[4];
        #pragma unroll
        for (int j4=0;j4<4;j4++){
            float4 a = *(const float4*)(hp + j4*4);
            float4 c = *(const float4*)(yp + j4*4);
            float4 d = *(const float4*)(gp + j4*4);
            v[j4] = make_float4(a.x+c.x+d.x, a.y+c.y+d.y, a.z+c.z+d.z, a.w+c.w+d.w);
        }
        conv_store16(v, &AsH[row*UKP + chunk*8], &AsL[row*UKP + chunk*8]);
    }
    // B: Wu[384][64] presplit once. 1536 items of 16 floats, 3 per thread.
    #pragma unroll
    for (int i=0;i<3;i++){
        int item = tid + i*512;
        int n = item >> 2, chunk = item & 3;
        const float* p = Wu + (size_t)n*NR + chunk*16;
        float4 v[4];
        #pragma unroll
        for (int j=0;j<4;j++) v[j] = *(const float4*)(p + j*4);
        conv_store16(v, &BsH[n*UKP + chunk*8], &BsL[n*UKP + chunk*8]);
    }
    if (tid < 384) sBu[tid] = bu[tid];
    __syncthreads();

    float acc[12][4] = {};
    #pragma unroll
    for (int cc=0; cc<4; cc++){
        uint32_t aH[4], aL[4];
        int offa = (wm*16 + qr)*UKP + cc*8 + 2*t4;
        load_afrag(&AsH[offa], &AsL[offa], UKP, aH, aL);
        #pragma unroll
        for (int nt=0; nt<12; nt++){
            int n = wn*96 + nt*8 + qr;
            uint2 bh = *(const uint2*)&BsH[n*UKP + cc*8 + 2*t4];
            uint2 bl = *(const uint2*)&BsL[n*UKP + cc*8 + 2*t4];
            mma3(acc[nt], aH, aL, bh.x, bh.y, bl.x, bl.y);
        }
    }
    #pragma unroll
    for (int nt=0; nt<12; nt++){
        int col = wn*96 + nt*8 + 2*t4;
        float b0 = sBu[col], b1 = sBu[col+1];
        int row = m0 + wm*16 + qr;
        float* o = out + (size_t)row*NDIM + col;
        *(float2*)o            = make_float2(acc[nt][0]+b0, acc[nt][1]+b1);
        *(float2*)(o + 8*NDIM) = make_float2(acc[nt][2]+b0, acc[nt][3]+b1);
    }
}

extern "C" void kernel_launch(void* const* d_in, const int* in_sizes, int n_in,
                              void* d_out, int out_size)
{
    const float* input = (const float*)d_in[0];
    const float* subU  = (const float*)d_in[1];
    const void*  idx   = d_in[2];
    const float* Wd    = (const float*)d_in[3];
    const float* bd    = (const float*)d_in[4];
    const float* Wu    = (const float*)d_in[5];
    const float* bu    = (const float*)d_in[6];
    const float* Wa    = (const float*)d_in[7];
    const float* ba    = (const float*)d_in[8];
    const float* ga    = (const float*)d_in[9];
    const float* be    = (const float*)d_in[10];
    float* out = (float*)d_out;
    (void)in_sizes; (void)n_in; (void)out_size;

    cudaFuncSetAttribute(down_kernel,  cudaFuncAttributeMaxDynamicSharedMemorySize, DK_SMEM);
    cudaFuncSetAttribute(group_kernel, cudaFuncAttributeMaxDynamicSharedMemorySize, GK_SMEM);
    cudaFuncSetAttribute(up_kernel,    cudaFuncAttributeMaxDynamicSharedMemorySize, UK_SMEM);

    probe_idx_kernel<<<1, 128>>>((const unsigned int*)idx);
    convert_idx_kernel<<<(2*MT + 255)/256, 256>>>(idx);
    down_kernel<<<MT/128, 256, DK_SMEM>>>(input, Wd, bd);
    group_kernel<<<NB*NG, 256, GK_SMEM>>>(subU, Wa, ba, ga, be);
    up_kernel<<<MT/64, 512, UK_SMEM>>>(Wu, bu, out);
}

// round 17
// speedup vs baseline: 1.5210x; 1.0931x over previous
#include <cuda_runtime.h>
#include <cstdint>

#define NB 16
#define NN 8192
#define NDIM 384
#define NR 64
#define NG 128
#define MT (NB*NN)

__device__ __align__(256) float g_h[(size_t)MT*NR];
__device__ __align__(256) float g_y[(size_t)MT*NR];
__device__ __align__(256) int   g_idx[2*MT];
__device__ int g_is64;
// presplit weights (pair-permuted, same layout as smem tiles)
__device__ __align__(256) uint32_t g_wdH[24*64*8], g_wdL[24*64*8];   // Wd: kc<24, r<64
__device__ __align__(256) uint32_t g_wuH[384*4*8], g_wuL[384*4*8];   // Wu: r<384, kc<4
__device__ __align__(256) uint32_t g_waH[64*4*8],  g_waL[64*4*8];    // Wa: r<64, kc<4

__device__ __forceinline__ float silu_f(float x){ return x / (1.0f + __expf(-x)); }

// pack pair: low half = even-k, high half = odd-k; hi + residual-lo bf16
__device__ __forceinline__ void bf16pair(float e, float o, uint32_t& hp, uint32_t& lp){
    asm("cvt.rn.bf16x2.f32 %0, %1, %2;" : "=r"(hp) : "f"(o), "f"(e));
    float he = __uint_as_float(hp << 16);
    float ho = __uint_as_float(hp & 0xffff0000u);
    asm("cvt.rn.bf16x2.f32 %0, %1, %2;" : "=r"(lp) : "f"(o - ho), "f"(e - he));
}
__device__ __forceinline__ void bf16split1(float v, unsigned short& hs, unsigned short& ls){
    asm("cvt.rn.bf16.f32 %0, %1;" : "=h"(hs) : "f"(v));
    float hf = __uint_as_float(((uint32_t)hs) << 16);
    asm("cvt.rn.bf16.f32 %0, %1;" : "=h"(ls) : "f"(v - hf));
}
__device__ __forceinline__ void mma_bf16(float (&c)[4],
    uint32_t a0, uint32_t a1, uint32_t a2, uint32_t a3, uint32_t b0, uint32_t b1)
{
    asm volatile("mma.sync.aligned.m16n8k16.row.col.f32.bf16.bf16.f32 "
        "{%0,%1,%2,%3}, {%4,%5,%6,%7}, {%8,%9}, {%0,%1,%2,%3};\n"
        : "+f"(c[0]), "+f"(c[1]), "+f"(c[2]), "+f"(c[3])
        : "r"(a0), "r"(a1), "r"(a2), "r"(a3), "r"(b0), "r"(b1));
}
__device__ __forceinline__ void mma3(float (&c)[4],
    const uint32_t (&aH)[4], const uint32_t (&aL)[4],
    uint32_t bH0, uint32_t bH1, uint32_t bL0, uint32_t bL1)
{
    mma_bf16(c, aL[0],aL[1],aL[2],aL[3], bH0,bH1);
    mma_bf16(c, aH[0],aH[1],aH[2],aH[3], bL0,bL1);
    mma_bf16(c, aH[0],aH[1],aH[2],aH[3], bH0,bH1);
}
// slot permutation within an 8-pair (k16) chunk: pair q -> slot {0,2,4,6,1,3,5,7}[q]
__device__ __forceinline__ int slotof(int q){ return ((q&3)<<1) | (q>>2); }

// 16 consecutive-k floats -> presplit pair-permuted chunk (smem or global dst)
__device__ __forceinline__ void conv_store16(const float4* v, uint32_t* dH, uint32_t* dL){
    uint32_t h[8], l[8];
    #pragma unroll
    for (int j=0;j<4;j++){
        bf16pair(v[j].x, v[j].y, h[2*j],   l[2*j]);
        bf16pair(v[j].z, v[j].w, h[2*j+1], l[2*j+1]);
    }
    *(uint4*)dH     = make_uint4(h[0],h[4],h[1],h[5]);
    *(uint4*)(dH+4) = make_uint4(h[2],h[6],h[3],h[7]);
    *(uint4*)dL     = make_uint4(l[0],l[4],l[1],l[5]);
    *(uint4*)(dL+4) = make_uint4(l[2],l[6],l[3],l[7]);
}
__device__ __forceinline__ void load_afrag(const uint32_t* H, const uint32_t* L, int stride,
                                           uint32_t (&aH)[4], uint32_t (&aL)[4]){
    uint2 h0 = *(const uint2*)H;
    uint2 h1 = *(const uint2*)(H + 8*stride);
    uint2 l0 = *(const uint2*)L;
    uint2 l1 = *(const uint2*)(L + 8*stride);
    aH[0]=h0.x; aH[1]=h1.x; aH[2]=h0.y; aH[3]=h1.y;
    aL[0]=l0.x; aL[1]=l1.x; aL[2]=l0.y; aL[3]=l1.y;
}

__global__ void probe_idx_kernel(const unsigned int* __restrict__ w){
    __shared__ int ok;
    if (threadIdx.x == 0) ok = 1;
    __syncthreads();
    if (w[2*threadIdx.x + 1] != 0u) ok = 0;
    __syncthreads();
    if (threadIdx.x == 0) g_is64 = ok;
}
__global__ void convert_idx_kernel(const void* __restrict__ p){
    int i = blockIdx.x*blockDim.x + threadIdx.x;
    if (i >= 2*MT) return;
    if (g_is64) g_idx[i] = (int)((const long long*)p)[i];
    else        g_idx[i] = ((const int*)p)[i];
}

// ========== prep: presplit Wd / Wu / Wa into global (done once) =============
__global__ void prep_weights(const float* __restrict__ Wd,
                             const float* __restrict__ Wu,
                             const float* __restrict__ Wa)
{
    int t = blockIdx.x*256 + threadIdx.x;
    float4 v[4];
    if (t < 1536){                       // Wd: r<64, kc<24
        int r = t / 24, kc = t % 24;
        const float* p = Wd + (size_t)r*NDIM + kc*16;
        #pragma unroll
        for (int j=0;j<4;j++) v[j] = *(const float4*)(p + j*4);
        conv_store16(v, &g_wdH[((size_t)kc*64 + r)*8], &g_wdL[((size_t)kc*64 + r)*8]);
    } else if (t < 3072){                // Wu: r<384, kc<4
        int i = t - 1536;
        int r = i >> 2, kc = i & 3;
        const float* p = Wu + (size_t)r*NR + kc*16;
        #pragma unroll
        for (int j=0;j<4;j++) v[j] = *(const float4*)(p + j*4);
        conv_store16(v, &g_wuH[(size_t)i*8], &g_wuL[(size_t)i*8]);
    } else if (t < 3328){                // Wa: r<64, kc<4
        int i = t - 3072;
        int r = i >> 2, kc = i & 3;
        const float* p = Wa + (size_t)r*NR + kc*16;
        #pragma unroll
        for (int j=0;j<4;j++) v[j] = *(const float4*)(p + j*4);
        conv_store16(v, &g_waH[(size_t)i*8], &g_waL[(size_t)i*8]);
    }
}

// ========== K1: h = silu(X @ Wd^T + bd), bf16x3, BM=128 BN=64 BK=32 =========
// Double-buffered stages; B tiles copied from presplit global (no reconvert).
#define DKP 24
#define DK_BUF (128*DKP*2 + 64*DKP*2)
#define DK_SMEM (2*DK_BUF*4)
__global__ __launch_bounds__(256) void down_kernel(
    const float* __restrict__ A, const float* __restrict__ bd)
{
    extern __shared__ char smraw[];
    uint32_t* base = (uint32_t*)smraw;
    const int tid = threadIdx.x;
    const int wid = tid >> 5, lane = tid & 31;
    const int qr = lane >> 2, t4 = lane & 3;
    const int wm = wid & 3, wn = wid >> 2;          // 4m x 2n warps, warp 32m x 32n
    const int m0 = blockIdx.x * 128;
    const int arow = tid >> 1, achk = tid & 1;
    const bool doB = tid < 128;
    const int brow = tid >> 1, bchk = tid & 1;      // valid when doB

    float4 pa[4];
    uint4 pbh[2], pbl[2];
    {
        const float* p = A + (size_t)(m0+arow)*NDIM + achk*16;
        #pragma unroll
        for (int j=0;j<4;j++) pa[j] = *(const float4*)(p + j*4);
        if (doB){
            int kc = bchk;                                   // stage 0
            const uint4* sh = (const uint4*)&g_wdH[((size_t)kc*64 + brow)*8];
            const uint4* sl = (const uint4*)&g_wdL[((size_t)kc*64 + brow)*8];
            pbh[0]=sh[0]; pbh[1]=sh[1]; pbl[0]=sl[0]; pbl[1]=sl[1];
        }
    }
    {   // store stage 0 into buffer 0
        uint32_t* AsH = base;
        uint32_t* AsL = AsH + 128*DKP;
        uint32_t* BsH = AsL + 128*DKP;
        uint32_t* BsL = BsH + 64*DKP;
        conv_store16(pa, &AsH[arow*DKP + achk*8], &AsL[arow*DKP + achk*8]);
        if (doB){
            uint4* dh = (uint4*)&BsH[brow*DKP + bchk*8];
            uint4* dl = (uint4*)&BsL[brow*DKP + bchk*8];
            dh[0]=pbh[0]; dh[1]=pbh[1]; dl[0]=pbl[0]; dl[1]=pbl[1];
        }
    }
    __syncthreads();

    float acc[2][4][4] = {};
    for (int s = 0; s < 12; s++){
        uint32_t* cb  = base + (s&1)*DK_BUF;
        uint32_t* AsH = cb;
        uint32_t* AsL = AsH + 128*DKP;
        uint32_t* BsH = AsL + 128*DKP;
        uint32_t* BsL = BsH + 64*DKP;

        if (s < 11){   // prefetch next stage into regs
            const float* p = A + (size_t)(m0+arow)*NDIM + (s+1)*32 + achk*16;
            #pragma unroll
            for (int j=0;j<4;j++) pa[j] = *(const float4*)(p + j*4);
            if (doB){
                int kc = (s+1)*2 + bchk;
                const uint4* sh = (const uint4*)&g_wdH[((size_t)kc*64 + brow)*8];
                const uint4* sl = (const uint4*)&g_wdL[((size_t)kc*64 + brow)*8];
                pbh[0]=sh[0]; pbh[1]=sh[1]; pbl[0]=sl[0]; pbl[1]=sl[1];
            }
        }

        #pragma unroll
        for (int cc = 0; cc < 2; cc++){
            uint32_t aH[2][4], aL[2][4];
            #pragma unroll
            for (int mt=0; mt<2; mt++){
                int off = (wm*32 + mt*16 + qr)*DKP + cc*8 + 2*t4;
                load_afrag(&AsH[off], &AsL[off], DKP, aH[mt], aL[mt]);
            }
            #pragma unroll
            for (int nt=0; nt<4; nt++){
                int n = wn*32 + nt*8 + qr;
                uint2 bh = *(const uint2*)&BsH[n*DKP + cc*8 + 2*t4];
                uint2 bl = *(const uint2*)&BsL[n*DKP + cc*8 + 2*t4];
                #pragma unroll
                for (int mt=0; mt<2; mt++)
                    mma3(acc[mt][nt], aH[mt], aL[mt], bh.x, bh.y, bl.x, bl.y);
            }
        }

        if (s < 11){   // convert/copy next stage into the other buffer
            uint32_t* nb  = base + ((s+1)&1)*DK_BUF;
            uint32_t* nAsH = nb;
            uint32_t* nAsL = nAsH + 128*DKP;
            uint32_t* nBsH = nAsL + 128*DKP;
            uint32_t* nBsL = nBsH + 64*DKP;
            conv_store16(pa, &nAsH[arow*DKP + achk*8], &nAsL[arow*DKP + achk*8]);
            if (doB){
                uint4* dh = (uint4*)&nBsH[brow*DKP + bchk*8];
                uint4* dl = (uint4*)&nBsL[brow*DKP + bchk*8];
                dh[0]=pbh[0]; dh[1]=pbh[1]; dl[0]=pbl[0]; dl[1]=pbl[1];
            }
            __syncthreads();
        }
    }

    #pragma unroll
    for (int mt=0; mt<2; mt++){
        int row = m0 + wm*32 + mt*16 + qr;
        #pragma unroll
        for (int nt=0; nt<4; nt++){
            int col = wn*32 + nt*8 + 2*t4;
            float b0 = __ldg(bd+col), b1 = __ldg(bd+col+1);
            float* o = g_h + (size_t)row*NR + col;
            *(float2*)o = make_float2(silu_f(acc[mt][nt][0]+b0), silu_f(acc[mt][nt][1]+b1));
            *(float2*)(o + 8*NR) = make_float2(silu_f(acc[mt][nt][2]+b0), silu_f(acc[mt][nt][3]+b1));
        }
    }
}

// ========== K2: fused per-(b,g) branch, bf16x3 mma ==========================
#define GP 40
#define FFS 72
#define GK_SMEM ((8*64*GP + 3*64)*4)
__global__ __launch_bounds__(256) void group_kernel(
    const float* __restrict__ subU,
    const float* __restrict__ ba, const float* __restrict__ gamma,
    const float* __restrict__ beta)
{
    extern __shared__ char smraw[];
    uint32_t* b0H = (uint32_t*)smraw;
    uint32_t* b0L = b0H + 64*GP;
    uint32_t* b1H = b0L + 64*GP;
    uint32_t* b1L = b1H + 64*GP;
    uint32_t* b2H = b1L + 64*GP;
    uint32_t* b2L = b2H + 64*GP;
    uint32_t* b3H = b2L + 64*GP;
    uint32_t* b3L = b3H + 64*GP;
    float*    cGa = (float*)(b3L + 64*GP);
    float*    cBe = cGa + 64;
    float*    cBa = cBe + 64;
    float*    Ffp = (float*)b1H;

    const int tid = threadIdx.x;
    const int wid = tid >> 5, lane = tid & 31;
    const int qr = lane >> 2, t4 = lane & 3;
    const int wm = wid & 3, wn = wid >> 2;
    const int bg = blockIdx.x;
    const int b = bg >> 7, gg = bg & 127;
    const float* U = subU + ((size_t)(16 + b)*128 + gg)*4096;

    {
        int row = tid >> 2, chunk = tid & 3;
        float4 v[4];
        const float* p = U + row*64 + chunk*16;
        #pragma unroll
        for (int j=0;j<4;j++) v[j] = *(const float4*)(p + j*4);
        conv_store16(v, &b2H[row*GP + chunk*8], &b2L[row*GP + chunk*8]);
        // Wa tile: copy from presplit global
        int i = row*4 + chunk;
        const uint4* sh = (const uint4*)&g_waH[(size_t)i*8];
        const uint4* sl = (const uint4*)&g_waL[(size_t)i*8];
        uint4* dh = (uint4*)&b3H[row*GP + chunk*8];
        uint4* dl = (uint4*)&b3L[row*GP + chunk*8];
        dh[0]=sh[0]; dh[1]=sh[1]; dl[0]=sl[0]; dl[1]=sl[1];
    }
    #pragma unroll
    for (int rep=0; rep<2; rep++){
        int item = tid + rep*256;
        int tp = item & 31, sc = item >> 5;
        int t0 = 2*tp;
        int sl = (tp>>3)*8 + slotof(tp&7);
        float4 a0 = *(const float4*)(U + t0*64 + sc*4);
        float4 a1 = *(const float4*)(U + (t0+1)*64 + sc*4);
        float ea[4] = {a0.x,a0.y,a0.z,a0.w};
        float eo[4] = {a1.x,a1.y,a1.z,a1.w};
        #pragma unroll
        for (int jj=0;jj<4;jj++){
            uint32_t hp, lp;
            bf16pair(ea[jj], eo[jj], hp, lp);
            int s = sc*4 + jj;
            b0H[s*GP + sl] = hp; b0L[s*GP + sl] = lp;
        }
        int src0 = g_idx[b*NN + gg*64 + t0];
        int src1 = g_idx[b*NN + gg*64 + t0 + 1];
        float4 x0 = *(const float4*)(g_h + ((size_t)b*NN + src0)*NR + sc*4);
        float4 x1 = *(const float4*)(g_h + ((size_t)b*NN + src1)*NR + sc*4);
        float xa[4] = {x0.x,x0.y,x0.z,x0.w};
        float xb[4] = {x1.x,x1.y,x1.z,x1.w};
        #pragma unroll
        for (int jj=0;jj<4;jj++){
            uint32_t hp, lp;
            bf16pair(xa[jj], xb[jj], hp, lp);
            int s = sc*4 + jj;
            b1H[s*GP + sl] = hp; b1L[s*GP + sl] = lp;
        }
    }
    if (tid < 64){ cGa[tid]=gamma[tid]; cBe[tid]=beta[tid]; cBa[tid]=ba[tid]; }
    __syncthreads();

    float accF[4][4] = {};
    #pragma unroll
    for (int cc=0; cc<4; cc++){
        uint32_t aH[4], aL[4];
        int offa = (wm*16 + qr)*GP + cc*8 + 2*t4;
        load_afrag(&b0H[offa], &b0L[offa], GP, aH, aL);
        #pragma unroll
        for (int nt=0; nt<4; nt++){
            int n = wn*32 + nt*8 + qr;
            uint2 bh = *(const uint2*)&b1H[n*GP + cc*8 + 2*t4];
            uint2 bl = *(const uint2*)&b1L[n*GP + cc*8 + 2*t4];
            mma3(accF[nt], aH, aL, bh.x, bh.y, bl.x, bl.y);
        }
    }
    __syncthreads();
    #pragma unroll
    for (int nt=0; nt<4; nt++){
        int col = wn*32 + nt*8 + 2*t4;
        *(float2*)&Ffp[(wm*16+qr)*FFS + col]   = make_float2(accF[nt][0], accF[nt][1]);
        *(float2*)&Ffp[(wm*16+qr+8)*FFS + col] = make_float2(accF[nt][2], accF[nt][3]);
    }
    __syncthreads();

    {
        int row = tid >> 2, ch = tid & 3;
        float f[16];
        #pragma unroll
        for (int j=0;j<4;j++){
            float4 v = *(const float4*)&Ffp[row*FFS + ch*16 + j*4];
            f[4*j]=v.x; f[4*j+1]=v.y; f[4*j+2]=v.z; f[4*j+3]=v.w;
        }
        float ssum=0.f, ssq=0.f;
        #pragma unroll
        for (int j=0;j<16;j++){ ssum += f[j]; ssq += f[j]*f[j]; }
        ssum += __shfl_xor_sync(0xffffffffu, ssum, 1);
        ssq  += __shfl_xor_sync(0xffffffffu, ssq , 1);
        ssum += __shfl_xor_sync(0xffffffffu, ssum, 2);
        ssq  += __shfl_xor_sync(0xffffffffu, ssq , 2);
        float mean = ssum * (1.0f/64.0f);
        float var  = ssq  * (1.0f/64.0f) - mean*mean;
        float rstd = rsqrtf(var + 1e-5f);
        uint32_t h[8], l[8];
        #pragma unroll
        for (int q=0;q<8;q++){
            int k0 = ch*16 + 2*q;
            float e = (f[2*q]  -mean)*rstd*cGa[k0]   + cBe[k0];
            float o = (f[2*q+1]-mean)*rstd*cGa[k0+1] + cBe[k0+1];
            bf16pair(e, o, h[q], l[q]);
        }
        uint32_t* dH = &b0H[row*GP + ch*8];
        uint32_t* dL = &b0L[row*GP + ch*8];
        *(uint4*)dH     = make_uint4(h[0],h[4],h[1],h[5]);
        *(uint4*)(dH+4) = make_uint4(h[2],h[6],h[3],h[7]);
        *(uint4*)dL     = make_uint4(l[0],l[4],l[1],l[5]);
        *(uint4*)(dL+4) = make_uint4(l[2],l[6],l[3],l[7]);
    }
    __syncthreads();

    float accG[4][4] = {};
    #pragma unroll
    for (int cc=0; cc<4; cc++){
        uint32_t aH[4], aL[4];
        int offa = (wm*16 + qr)*GP + cc*8 + 2*t4;
        load_afrag(&b0H[offa], &b0L[offa], GP, aH, aL);
        #pragma unroll
        for (int nt=0; nt<4; nt++){
            int n = wn*32 + nt*8 + qr;
            uint2 bh = *(const uint2*)&b3H[n*GP + cc*8 + 2*t4];
            uint2 bl = *(const uint2*)&b3L[n*GP + cc*8 + 2*t4];
            mma3(accG[nt], aH, aL, bh.x, bh.y, bl.x, bl.y);
        }
    }
    __syncthreads();

    #pragma unroll
    for (int nt=0; nt<4; nt++){
        int colb = wn*32 + nt*8 + 2*t4;
        #pragma unroll
        for (int c=0; c<4; c++){
            int srow = wm*16 + qr + (c>>1)*8;
            int col  = colb + (c&1);
            float v = accF[nt][c] + silu_f(accG[nt][c] + cBa[col]);
            int sp = srow >> 1, half = srow & 1;
            int sl = (sp>>3)*8 + slotof(sp&7);
            unsigned short hs, ls;
            bf16split1(v, hs, ls);
            ((unsigned short*)(b3H + col*GP + sl))[half] = hs;
            ((unsigned short*)(b3L + col*GP + sl))[half] = ls;
        }
    }
    __syncthreads();

    float accY[4][4] = {};
    #pragma unroll
    for (int cc=0; cc<4; cc++){
        uint32_t aH[4], aL[4];
        int offa = (wm*16 + qr)*GP + cc*8 + 2*t4;
        load_afrag(&b2H[offa], &b2L[offa], GP, aH, aL);
        #pragma unroll
        for (int nt=0; nt<4; nt++){
            int n = wn*32 + nt*8 + qr;
            uint2 bh = *(const uint2*)&b3H[n*GP + cc*8 + 2*t4];
            uint2 bl = *(const uint2*)&b3L[n*GP + cc*8 + 2*t4];
            mma3(accY[nt], aH, aL, bh.x, bh.y, bl.x, bl.y);
        }
    }
    float* yout = g_y + ((size_t)b*NN + gg*64)*NR;
    #pragma unroll
    for (int nt=0; nt<4; nt++){
        int col = wn*32 + nt*8 + 2*t4;
        *(float2*)(yout + (size_t)(wm*16+qr)*NR + col)   = make_float2(accY[nt][0], accY[nt][1]);
        *(float2*)(yout + (size_t)(wm*16+qr+8)*NR + col) = make_float2(accY[nt][2], accY[nt][3]);
    }
}

// ========== K3: out = (h + y + gather(y,idx1)) @ Wu^T + bu ==================
// BM=64, BN=384, K=64. 512 thr = 16 warps (4m x 4n), warp 16m x 96n.
// A presplit on the fly (unique data); B copied from presplit global.
#define UKP 40
#define UK_SMEM ((64*UKP*2 + 384*UKP*2 + 384)*4)
__global__ __launch_bounds__(512) void up_kernel(
    const float* __restrict__ bu, float* __restrict__ out)
{
    extern __shared__ char smraw[];
    uint32_t* AsH = (uint32_t*)smraw;
    uint32_t* AsL = AsH + 64*UKP;
    uint32_t* BsH = AsL + 64*UKP;
    uint32_t* BsL = BsH + 384*UKP;
    float*    sBu = (float*)(BsL + 384*UKP);
    const int tid = threadIdx.x;
    const int wid = tid >> 5, lane = tid & 31;
    const int qr = lane >> 2, t4 = lane & 3;
    const int wm = wid & 3, wn = wid >> 2;
    const int m0 = blockIdx.x * 64;

    if (tid < 256){   // A: fused combine, presplit
        int row = tid >> 2, chunk = tid & 3;
        int grow = m0 + row;
        int b = grow >> 13, j = grow & (NN-1);
        int src = g_idx[MT + (b<<13) + j];
        const float* hp = g_h + (size_t)grow*NR + chunk*16;
        const float* yp = g_y + (size_t)grow*NR + chunk*16;
        const float* gp = g_y + ((size_t)((b<<13) + src))*NR + chunk*16;
        float4 v[4];
        #pragma unroll
        for (int j4=0;j4<4;j4++){
            float4 a = *(const float4*)(hp + j4*4);
            float4 c = *(const float4*)(yp + j4*4);
            float4 d = *(const float4*)(gp + j4*4);
            v[j4] = make_float4(a.x+c.x+d.x, a.y+c.y+d.y, a.z+c.z+d.z, a.w+c.w+d.w);
        }
        conv_store16(v, &AsH[row*UKP + chunk*8], &AsL[row*UKP + chunk*8]);
    }
    // B: copy presplit Wu. 1536 chunks per array, 3072 total, 6 per thread.
    #pragma unroll
    for (int i=0;i<6;i++){
        int item = tid + i*512;
        int isL = item >= 1536;
        int idx = item - (isL ? 1536 : 0);      // r*4 + kc
        int r = idx >> 2, kc = idx & 3;
        const uint4* s = (const uint4*)((isL ? g_wuL : g_wuH) + (size_t)idx*8);
        uint4* d = (uint4*)((isL ? BsL : BsH) + r*UKP + kc*8);
        d[0] = s[0]; d[1] = s[1];
    }
    if (tid < 384) sBu[tid] = bu[tid];
    __syncthreads();

    float acc[12][4] = {};
    #pragma unroll
    for (int cc=0; cc<4; cc++){
        uint32_t aH[4], aL[4];
        int offa = (wm*16 + qr)*UKP + cc*8 + 2*t4;
        load_afrag(&AsH[offa], &AsL[offa], UKP, aH, aL);
        #pragma unroll
        for (int nt=0; nt<12; nt++){
            int n = wn*96 + nt*8 + qr;
            uint2 bh = *(const uint2*)&BsH[n*UKP + cc*8 + 2*t4];
            uint2 bl = *(const uint2*)&BsL[n*UKP + cc*8 + 2*t4];
            mma3(acc[nt], aH, aL, bh.x, bh.y, bl.x, bl.y);
        }
    }
    #pragma unroll
    for (int nt=0; nt<12; nt++){
        int col = wn*96 + nt*8 + 2*t4;
        float b0 = sBu[col], b1 = sBu[col+1];
        int row = m0 + wm*16 + qr;
        float* o = out + (size_t)row*NDIM + col;
        *(float2*)o            = make_float2(acc[nt][0]+b0, acc[nt][1]+b1);
        *(float2*)(o + 8*NDIM) = make_float2(acc[nt][2]+b0, acc[nt][3]+b1);
    }
}

extern "C" void kernel_launch(void* const* d_in, const int* in_sizes, int n_in,
                              void* d_out, int out_size)
{
    const float* input = (const float*)d_in[0];
    const float* subU  = (const float*)d_in[1];
    const void*  idx   = d_in[2];
    const float* Wd    = (const float*)d_in[3];
    const float* bd    = (const float*)d_in[4];
    const float* Wu    = (const float*)d_in[5];
    const float* bu    = (const float*)d_in[6];
    const float* Wa    = (const float*)d_in[7];
    const float* ba    = (const float*)d_in[8];
    const float* ga    = (const float*)d_in[9];
    const float* be    = (const float*)d_in[10];
    float* out = (float*)d_out;
    (void)in_sizes; (void)n_in; (void)out_size;

    cudaFuncSetAttribute(down_kernel,  cudaFuncAttributeMaxDynamicSharedMemorySize, DK_SMEM);
    cudaFuncSetAttribute(group_kernel, cudaFuncAttributeMaxDynamicSharedMemorySize, GK_SMEM);
    cudaFuncSetAttribute(up_kernel,    cudaFuncAttributeMaxDynamicSharedMemorySize, UK_SMEM);

    probe_idx_kernel<<<1, 128>>>((const unsigned int*)idx);
    convert_idx_kernel<<<(2*MT + 255)/256, 256>>>(idx);
    prep_weights<<<14, 256>>>(Wd, Wu, Wa);
    down_kernel<<<MT/128, 256, DK_SMEM>>>(input, bd);
    group_kernel<<<NB*NG, 256, GK_SMEM>>>(subU, ba, ga, be);
    up_kernel<<<MT/64, 512, UK_SMEM>>>(bu, out);
}